// round 12
// baseline (speedup 1.0000x reference)
#include <cuda_runtime.h>
#include <math.h>

#define N_NODES 4096
#define FIN     256
#define NHEAD   4
#define FHID    64
#define FFIN    64
#define NPROJ   16
#define MAXD    128

// ---------------- scratch ----------------
__device__ int   g_cols[2][N_NODES][MAXD];
__device__ int   g_deg [2][N_NODES];
__device__ float g_Wh  [N_NODES][512];      // x @ Wcat   (cols: g*256 + h*64 + f)
__device__ float g_s1t [2][N_NODES][4];     // layer-1 src logits, 4 heads packed
__device__ float g_s2t [2][N_NODES][4];     // layer-1 dst logits, 4 heads packed
__device__ float g_hcat[2][N_NODES][256];   // layer-1 outputs (head-concat)
__device__ float g_Wh2 [2][N_NODES][64];
__device__ float g_s1o [2][N_NODES];
__device__ float g_s2o [2][N_NODES];

__device__ __forceinline__ float lkexp(float z) {
    z = z >= 0.f ? z : 0.2f * z;
    return __expf(z);
}
__device__ __forceinline__ float elu1(float v) {
    return v > 0.f ? v : (__expf(v) - 1.f);
}

// =====================================================================
// CSR build (standalone, low regs, MLP=4): one warp per (graph,row).
// =====================================================================
__device__ __forceinline__ void place_bits(unsigned nb, int cb, int& pos, int* __restrict__ row) {
    while (nb) {
        int b = __ffs(nb) - 1;
        nb &= nb - 1;
        if (pos < MAXD) row[pos] = cb + b;
        pos++;
    }
}

__global__ void csr_build(const float* __restrict__ m0, const float* __restrict__ m1) {
    int tid  = threadIdx.x;
    int w    = blockIdx.x * 8 + (tid >> 5);
    int lane = tid & 31;
    int g = w >> 12, r = w & 4095;
    const float4* mask = (const float4*)((g ? m1 : m0) + (size_t)r * N_NODES);
    int* row = &g_cols[g][r][0];
    int cnt = 0;
    for (int jb = 0; jb < 1024; jb += 128) {
        float4 v0 = mask[jb + lane];
        float4 v1 = mask[jb + 32 + lane];
        float4 v2 = mask[jb + 64 + lane];
        float4 v3 = mask[jb + 96 + lane];
        unsigned n0 = (v0.x > 0.f) | ((v0.y > 0.f) << 1) | ((v0.z > 0.f) << 2) | ((v0.w > 0.f) << 3);
        unsigned n1 = (v1.x > 0.f) | ((v1.y > 0.f) << 1) | ((v1.z > 0.f) << 2) | ((v1.w > 0.f) << 3);
        unsigned n2 = (v2.x > 0.f) | ((v2.y > 0.f) << 1) | ((v2.z > 0.f) << 2) | ((v2.w > 0.f) << 3);
        unsigned n3 = (v3.x > 0.f) | ((v3.y > 0.f) << 1) | ((v3.z > 0.f) << 2) | ((v3.w > 0.f) << 3);
        int c = __popc(n0) + __popc(n1) + __popc(n2) + __popc(n3);
        int s = c;
        #pragma unroll
        for (int off = 1; off < 32; off <<= 1) {
            int t = __shfl_up_sync(0xffffffffu, s, off);
            if (lane >= off) s += t;
        }
        int pos = cnt + s - c;
        cnt += __shfl_sync(0xffffffffu, s, 31);
        if (c) {
            place_bits(n0, (jb + lane) * 4,      pos, row);
            place_bits(n1, (jb + 32 + lane) * 4, pos, row);
            place_bits(n2, (jb + 64 + lane) * 4, pos, row);
            place_bits(n3, (jb + 96 + lane) * 4, pos, row);
        }
    }
    if (lane == 0) g_deg[g][r] = cnt < MAXD ? cnt : MAXD;
}

// =====================================================================
// GEMM1: Wh = x @ Wcat, tile 128x64, 8x4 microtile, double-buffered.
// grid (32, 8) = 256 blocks, 256 threads. + s1/s2 epilogue.
// =====================================================================
__global__ void __launch_bounds__(256) gemm1(
        const float* __restrict__ x,
        const float* __restrict__ W1, const float* __restrict__ W2,
        const float* __restrict__ a1, const float* __restrict__ a2) {
    __shared__ float As[2][16][132];
    __shared__ float Bs[2][16][64];
    int tid = threadIdx.x;
    int m0r = blockIdx.x * 128;
    int by  = blockIdx.y;                 // 0..7
    int gsel = by >> 2, h = by & 3;
    const float* W  = gsel ? W2 : W1;     // [4,256,64]
    const float* av = (gsel ? a2 : a1) + h * 128;
    int tx = tid & 15, ty = tid >> 4;     // ty 0..15 -> 8 rows each

    // loaders: A 128x16 = 512 f4 (2/thread), B 16x64 = 256 f4 (1/thread)
    int a_m0 = tid >> 2,         a_k40 = tid & 3;
    int a_m1 = (256 + tid) >> 2, a_k41 = (256 + tid) & 3;
    int bk = tid >> 4, bn = (tid & 15) * 4;
    const float* Ap0 = x + (size_t)(m0r + a_m0) * FIN;
    const float* Ap1 = x + (size_t)(m0r + a_m1) * FIN;
    const float* Bbase = W + (size_t)h * FIN * FHID;

    float4 fa0 = *(const float4*)(Ap0 + a_k40 * 4);
    float4 fa1 = *(const float4*)(Ap1 + a_k41 * 4);
    float4 fb  = *(const float4*)(Bbase + (size_t)bk * FHID + bn);
    As[0][a_k40 * 4 + 0][a_m0] = fa0.x; As[0][a_k40 * 4 + 1][a_m0] = fa0.y;
    As[0][a_k40 * 4 + 2][a_m0] = fa0.z; As[0][a_k40 * 4 + 3][a_m0] = fa0.w;
    As[0][a_k41 * 4 + 0][a_m1] = fa1.x; As[0][a_k41 * 4 + 1][a_m1] = fa1.y;
    As[0][a_k41 * 4 + 2][a_m1] = fa1.z; As[0][a_k41 * 4 + 3][a_m1] = fa1.w;
    *(float4*)&Bs[0][bk][bn] = fb;
    __syncthreads();

    float acc[8][4] = {};
    #pragma unroll
    for (int t = 0; t < 16; t++) {
        int cur = t & 1;
        if (t < 15) {
            int kb = (t + 1) * 16;
            fa0 = *(const float4*)(Ap0 + kb + a_k40 * 4);
            fa1 = *(const float4*)(Ap1 + kb + a_k41 * 4);
            fb  = *(const float4*)(Bbase + (size_t)(kb + bk) * FHID + bn);
        }
        #pragma unroll
        for (int kk = 0; kk < 16; kk++) {
            float4 av0 = *(const float4*)&As[cur][kk][ty * 8];
            float4 av1 = *(const float4*)&As[cur][kk][ty * 8 + 4];
            float4 bv  = *(const float4*)&Bs[cur][kk][tx * 4];
            float a[8] = {av0.x, av0.y, av0.z, av0.w, av1.x, av1.y, av1.z, av1.w};
            float b[4] = {bv.x, bv.y, bv.z, bv.w};
            #pragma unroll
            for (int r = 0; r < 8; r++)
                #pragma unroll
                for (int c = 0; c < 4; c++)
                    acc[r][c] += a[r] * b[c];
        }
        if (t < 15) {
            int nxt = cur ^ 1;
            As[nxt][a_k40 * 4 + 0][a_m0] = fa0.x; As[nxt][a_k40 * 4 + 1][a_m0] = fa0.y;
            As[nxt][a_k40 * 4 + 2][a_m0] = fa0.z; As[nxt][a_k40 * 4 + 3][a_m0] = fa0.w;
            As[nxt][a_k41 * 4 + 0][a_m1] = fa1.x; As[nxt][a_k41 * 4 + 1][a_m1] = fa1.y;
            As[nxt][a_k41 * 4 + 2][a_m1] = fa1.z; As[nxt][a_k41 * 4 + 3][a_m1] = fa1.w;
            *(float4*)&Bs[nxt][bk][bn] = fb;
        }
        __syncthreads();
    }

    int n0 = by * 64;
    #pragma unroll
    for (int r = 0; r < 8; r++) {
        int m = m0r + ty * 8 + r;
        float4 v = make_float4(acc[r][0], acc[r][1], acc[r][2], acc[r][3]);
        *(float4*)&g_Wh[m][n0 + tx * 4] = v;
    }
    float a_s[4], a_d[4];
    #pragma unroll
    for (int c = 0; c < 4; c++) {
        a_s[c] = __ldg(av + tx * 4 + c);
        a_d[c] = __ldg(av + 64 + tx * 4 + c);
    }
    #pragma unroll
    for (int r = 0; r < 8; r++) {
        float s1 = 0.f, s2 = 0.f;
        #pragma unroll
        for (int c = 0; c < 4; c++) { s1 += acc[r][c] * a_s[c]; s2 += acc[r][c] * a_d[c]; }
        #pragma unroll
        for (int off = 1; off < 16; off <<= 1) {
            s1 += __shfl_xor_sync(0xffffffffu, s1, off);
            s2 += __shfl_xor_sync(0xffffffffu, s2, off);
        }
        if (tx == 0) {
            int m = m0r + ty * 8 + r;
            g_s1t[gsel][m][h] = s1;
            g_s2t[gsel][m][h] = s2;
        }
    }
}

// ---- 4-head gather chunk (attn1) ----
__device__ __forceinline__ void gat_chunk1(const float* __restrict__ tab, int lim,
                                           int cj, float4 ej,
                                           float& ax0, float& ay0, float& ax1, float& ay1,
                                           float& ax2, float& ay2, float& ax3, float& ay3) {
    int kk = 0;
    for (; kk + 2 <= lim; kk += 2) {
        int   ca  = __shfl_sync(0xffffffffu, cj, kk);
        int   cb  = __shfl_sync(0xffffffffu, cj, kk + 1);
        float ea0 = __shfl_sync(0xffffffffu, ej.x, kk);
        float ea1 = __shfl_sync(0xffffffffu, ej.y, kk);
        float ea2 = __shfl_sync(0xffffffffu, ej.z, kk);
        float ea3 = __shfl_sync(0xffffffffu, ej.w, kk);
        float eb0 = __shfl_sync(0xffffffffu, ej.x, kk + 1);
        float eb1 = __shfl_sync(0xffffffffu, ej.y, kk + 1);
        float eb2 = __shfl_sync(0xffffffffu, ej.z, kk + 1);
        float eb3 = __shfl_sync(0xffffffffu, ej.w, kk + 1);
        const float* ra = tab + (size_t)ca * 512;
        const float* rb = tab + (size_t)cb * 512;
        float2 va0 = *(const float2*)(ra);
        float2 va1 = *(const float2*)(ra + 64);
        float2 va2 = *(const float2*)(ra + 128);
        float2 va3 = *(const float2*)(ra + 192);
        float2 vb0 = *(const float2*)(rb);
        float2 vb1 = *(const float2*)(rb + 64);
        float2 vb2 = *(const float2*)(rb + 128);
        float2 vb3 = *(const float2*)(rb + 192);
        ax0 += ea0 * va0.x + eb0 * vb0.x;  ay0 += ea0 * va0.y + eb0 * vb0.y;
        ax1 += ea1 * va1.x + eb1 * vb1.x;  ay1 += ea1 * va1.y + eb1 * vb1.y;
        ax2 += ea2 * va2.x + eb2 * vb2.x;  ay2 += ea2 * va2.y + eb2 * vb2.y;
        ax3 += ea3 * va3.x + eb3 * vb3.x;  ay3 += ea3 * va3.y + eb3 * vb3.y;
    }
    if (kk < lim) {
        int   ca  = __shfl_sync(0xffffffffu, cj, kk);
        float ea0 = __shfl_sync(0xffffffffu, ej.x, kk);
        float ea1 = __shfl_sync(0xffffffffu, ej.y, kk);
        float ea2 = __shfl_sync(0xffffffffu, ej.z, kk);
        float ea3 = __shfl_sync(0xffffffffu, ej.w, kk);
        const float* ra = tab + (size_t)ca * 512;
        float2 va0 = *(const float2*)(ra);
        float2 va1 = *(const float2*)(ra + 64);
        float2 va2 = *(const float2*)(ra + 128);
        float2 va3 = *(const float2*)(ra + 192);
        ax0 += ea0 * va0.x;  ay0 += ea0 * va0.y;
        ax1 += ea1 * va1.x;  ay1 += ea1 * va1.y;
        ax2 += ea2 * va2.x;  ay2 += ea2 * va2.y;
        ax3 += ea3 * va3.x;  ay3 += ea3 * va3.y;
    }
}

// =====================================================================
// Layer-1 attention: ONE warp per (node, graph), all 4 heads together.
// =====================================================================
__global__ void attn_layer1() {
    int tid  = threadIdx.x;
    int lane = tid & 31;
    int w    = tid >> 5;
    int n    = w >> 1;
    int g    = w & 1;
    int i    = blockIdx.x * 4 + n;

    int d = g_deg[g][i];
    float4 s1 = *(const float4*)&g_s1t[g][i][0];

    int c0 = 0, c1 = 0;
    float4 e0 = make_float4(0.f, 0.f, 0.f, 0.f);
    float4 e1 = make_float4(0.f, 0.f, 0.f, 0.f);
    if (lane < d) {
        c0 = g_cols[g][i][lane];
        float4 s2 = *(const float4*)&g_s2t[g][c0][0];
        e0.x = lkexp(s1.x + s2.x);  e0.y = lkexp(s1.y + s2.y);
        e0.z = lkexp(s1.z + s2.z);  e0.w = lkexp(s1.w + s2.w);
    }
    if (lane + 32 < d) {
        c1 = g_cols[g][i][lane + 32];
        float4 s2 = *(const float4*)&g_s2t[g][c1][0];
        e1.x = lkexp(s1.x + s2.x);  e1.y = lkexp(s1.y + s2.y);
        e1.z = lkexp(s1.z + s2.z);  e1.w = lkexp(s1.w + s2.w);
    }
    float sx = e0.x + e1.x, sy = e0.y + e1.y, sz = e0.z + e1.z, sw = e0.w + e1.w;
    #pragma unroll
    for (int off = 16; off; off >>= 1) {
        sx += __shfl_xor_sync(0xffffffffu, sx, off);
        sy += __shfl_xor_sync(0xffffffffu, sy, off);
        sz += __shfl_xor_sync(0xffffffffu, sz, off);
        sw += __shfl_xor_sync(0xffffffffu, sw, off);
    }
    float ix = 1.f / sx, iy = 1.f / sy, iz = 1.f / sz, iw = 1.f / sw;

    const float* tab = &g_Wh[0][g * 256 + 2 * lane];
    float ax0 = 0.f, ay0 = 0.f, ax1 = 0.f, ay1 = 0.f;
    float ax2 = 0.f, ay2 = 0.f, ax3 = 0.f, ay3 = 0.f;
    int lim0 = d < 32 ? d : 32;
    int lim1 = d - 32; lim1 = lim1 < 0 ? 0 : lim1;
    gat_chunk1(tab, lim0, c0, e0, ax0, ay0, ax1, ay1, ax2, ay2, ax3, ay3);
    gat_chunk1(tab, lim1, c1, e1, ax0, ay0, ax1, ay1, ax2, ay2, ax3, ay3);

    float* orow = &g_hcat[g][i][2 * lane];
    float2 o;
    o.x = elu1(ax0 * ix);  o.y = elu1(ay0 * ix);  *(float2*)(orow)       = o;
    o.x = elu1(ax1 * iy);  o.y = elu1(ay1 * iy);  *(float2*)(orow + 64)  = o;
    o.x = elu1(ax2 * iz);  o.y = elu1(ay2 * iz);  *(float2*)(orow + 128) = o;
    o.x = elu1(ax3 * iw);  o.y = elu1(ay3 * iw);  *(float2*)(orow + 192) = o;
}

// =====================================================================
// GEMM2 (K-split): Wh2_g = hcat_g @ Wo_g, tile 32x64, 256 threads =
// 2 k-groups x 128; each group 4x4 microtile over K/2, smem reduce.
// grid (128, 2), double-buffered. + s1o/s2o epilogue.
// =====================================================================
__global__ void __launch_bounds__(256) gemm2f(
        const float* __restrict__ Wo1, const float* __restrict__ Wo2,
        const float* __restrict__ ao1, const float* __restrict__ ao2) {
    __shared__ float As[2][2][16][36];   // [kg][buf][k][m]
    __shared__ float Bs[2][2][16][64];   // [kg][buf][k][n]
    __shared__ float red[32][64];
    int g = blockIdx.y;
    int m0r = blockIdx.x * 32;
    const float* A  = &g_hcat[g][0][0];
    const float* B  = g ? Wo2 : Wo1;
    const float* ao = g ? ao2 : ao1;
    int tid  = threadIdx.x;
    int kg   = tid >> 7;                  // 0/1: K halves
    int tloc = tid & 127;
    int tx = tloc & 15, ty = tloc >> 4;   // ty 0..7
    int am = tloc >> 2, ak4 = tloc & 3;   // A loaders: 128 f4
    int bk0 = tloc >> 4, bc0 = (tloc & 15) * 4;
    int bk1 = (128 + tloc) >> 4, bc1 = ((128 + tloc) & 15) * 4;
    int kbase = kg * 128;
    const float* Aptr = A + (size_t)(m0r + am) * 256 + kbase;
    const float* Bptr = B + (size_t)kbase * 64;

    float4 fa  = *(const float4*)(Aptr + ak4 * 4);
    float4 fb0 = *(const float4*)(Bptr + (size_t)bk0 * 64 + bc0);
    float4 fb1 = *(const float4*)(Bptr + (size_t)bk1 * 64 + bc1);
    As[kg][0][ak4 * 4 + 0][am] = fa.x; As[kg][0][ak4 * 4 + 1][am] = fa.y;
    As[kg][0][ak4 * 4 + 2][am] = fa.z; As[kg][0][ak4 * 4 + 3][am] = fa.w;
    *(float4*)&Bs[kg][0][bk0][bc0] = fb0;
    *(float4*)&Bs[kg][0][bk1][bc1] = fb1;
    __syncthreads();

    float acc[4][4] = {};
    #pragma unroll
    for (int t = 0; t < 8; t++) {
        int cur = t & 1;
        if (t < 7) {
            int kb = (t + 1) * 16;
            fa  = *(const float4*)(Aptr + kb + ak4 * 4);
            fb0 = *(const float4*)(Bptr + (size_t)(kb + bk0) * 64 + bc0);
            fb1 = *(const float4*)(Bptr + (size_t)(kb + bk1) * 64 + bc1);
        }
        #pragma unroll
        for (int kk = 0; kk < 16; kk++) {
            float4 av = *(const float4*)&As[kg][cur][kk][ty * 4];
            float4 bv = *(const float4*)&Bs[kg][cur][kk][tx * 4];
            float a[4] = {av.x, av.y, av.z, av.w};
            float b[4] = {bv.x, bv.y, bv.z, bv.w};
            #pragma unroll
            for (int r = 0; r < 4; r++)
                #pragma unroll
                for (int c = 0; c < 4; c++)
                    acc[r][c] += a[r] * b[c];
        }
        if (t < 7) {
            int nxt = cur ^ 1;
            As[kg][nxt][ak4 * 4 + 0][am] = fa.x; As[kg][nxt][ak4 * 4 + 1][am] = fa.y;
            As[kg][nxt][ak4 * 4 + 2][am] = fa.z; As[kg][nxt][ak4 * 4 + 3][am] = fa.w;
            *(float4*)&Bs[kg][nxt][bk0][bc0] = fb0;
            *(float4*)&Bs[kg][nxt][bk1][bc1] = fb1;
        }
        __syncthreads();
    }

    if (kg == 1) {
        #pragma unroll
        for (int r = 0; r < 4; r++) {
            float4 v = make_float4(acc[r][0], acc[r][1], acc[r][2], acc[r][3]);
            *(float4*)&red[ty * 4 + r][tx * 4] = v;
        }
    }
    __syncthreads();
    if (kg == 0) {
        #pragma unroll
        for (int r = 0; r < 4; r++) {
            float4 v = *(const float4*)&red[ty * 4 + r][tx * 4];
            acc[r][0] += v.x; acc[r][1] += v.y; acc[r][2] += v.z; acc[r][3] += v.w;
        }
        #pragma unroll
        for (int r = 0; r < 4; r++) {
            int m = m0r + ty * 4 + r;
            float4 v = make_float4(acc[r][0], acc[r][1], acc[r][2], acc[r][3]);
            *(float4*)&g_Wh2[g][m][tx * 4] = v;
        }
        float a_s[4], a_d[4];
        #pragma unroll
        for (int c = 0; c < 4; c++) {
            a_s[c] = __ldg(ao + tx * 4 + c);
            a_d[c] = __ldg(ao + 64 + tx * 4 + c);
        }
        #pragma unroll
        for (int r = 0; r < 4; r++) {
            float s1 = 0.f, s2 = 0.f;
            #pragma unroll
            for (int c = 0; c < 4; c++) { s1 += acc[r][c] * a_s[c]; s2 += acc[r][c] * a_d[c]; }
            #pragma unroll
            for (int off = 1; off < 16; off <<= 1) {
                s1 += __shfl_xor_sync(0xffffffffu, s1, off);
                s2 += __shfl_xor_sync(0xffffffffu, s2, off);
            }
            if (tx == 0) {
                int m = m0r + ty * 4 + r;
                g_s1o[g][m] = s1;
                g_s2o[g][m] = s2;
            }
        }
    }
}

// ---- scalar gather chunk (attn2), MLP=4, stride 64 floats ----
__device__ __forceinline__ void gat_chunk2(const float* __restrict__ tab, int lim,
                                           int cj, float ej, float& ax, float& ay) {
    int kk = 0;
    for (; kk + 4 <= lim; kk += 4) {
        int   c0 = __shfl_sync(0xffffffffu, cj, kk);
        int   c1 = __shfl_sync(0xffffffffu, cj, kk + 1);
        int   c2 = __shfl_sync(0xffffffffu, cj, kk + 2);
        int   c3 = __shfl_sync(0xffffffffu, cj, kk + 3);
        float e0 = __shfl_sync(0xffffffffu, ej, kk);
        float e1 = __shfl_sync(0xffffffffu, ej, kk + 1);
        float e2 = __shfl_sync(0xffffffffu, ej, kk + 2);
        float e3 = __shfl_sync(0xffffffffu, ej, kk + 3);
        float2 v0 = *(const float2*)(tab + (size_t)c0 * 64);
        float2 v1 = *(const float2*)(tab + (size_t)c1 * 64);
        float2 v2 = *(const float2*)(tab + (size_t)c2 * 64);
        float2 v3 = *(const float2*)(tab + (size_t)c3 * 64);
        ax += e0 * v0.x + e1 * v1.x + e2 * v2.x + e3 * v3.x;
        ay += e0 * v0.y + e1 * v1.y + e2 * v2.y + e3 * v3.y;
    }
    for (; kk < lim; kk++) {
        int   c = __shfl_sync(0xffffffffu, cj, kk);
        float e = __shfl_sync(0xffffffffu, ej, kk);
        float2 v = *(const float2*)(tab + (size_t)c * 64);
        ax += e * v.x;
        ay += e * v.y;
    }
}

// =====================================================================
// Layer-2 attention + ELU + semantic fusion.
// =====================================================================
__global__ void attn2_final(const float* __restrict__ Wp1, const float* __restrict__ bp1,
                            const float* __restrict__ Wp2, float* __restrict__ out) {
    int tid  = threadIdx.x;
    int lane = tid & 31;
    int w    = tid >> 5;        // 0..7
    int n    = w >> 1;          // node slot 0..3
    int g    = w & 1;
    int i    = blockIdx.x * 4 + n;

    __shared__ float se[4][2][64];
    __shared__ float sw[4][2];

    int d = g_deg[g][i];
    float s1v = g_s1o[g][i];
    int c0 = 0, c1 = 0;
    float e0 = 0.f, e1 = 0.f;
    if (lane < d) {
        c0 = g_cols[g][i][lane];
        e0 = lkexp(s1v + g_s2o[g][c0]);
    }
    if (lane + 32 < d) {
        c1 = g_cols[g][i][lane + 32];
        e1 = lkexp(s1v + g_s2o[g][c1]);
    }
    float sum = e0 + e1;
    #pragma unroll
    for (int off = 16; off; off >>= 1) sum += __shfl_xor_sync(0xffffffffu, sum, off);
    float inv = 1.f / sum;

    const float* tab = &g_Wh2[g][0][2 * lane];
    float ax = 0.f, ay = 0.f;
    int lim0 = d < 32 ? d : 32;
    int lim1 = d - 32; lim1 = lim1 < 0 ? 0 : lim1;
    gat_chunk2(tab, lim0, c0, e0, ax, ay);
    gat_chunk2(tab, lim1, c1, e1, ax, ay);

    ax *= inv; ay *= inv;
    se[n][g][2 * lane]     = elu1(ax);
    se[n][g][2 * lane + 1] = elu1(ay);
    __syncthreads();

    if (tid < 128) {
        int pn = tid >> 5, pg = (tid >> 4) & 1, p = tid & 15;
        float s = __ldg(bp1 + p);
        #pragma unroll
        for (int f = 0; f < 64; f++) s += se[pn][pg][f] * __ldg(Wp1 + f * NPROJ + p);
        float e2x = __expf(2.f * s);
        float t = __fdividef(e2x - 1.f, e2x + 1.f);
        float wv = t * __ldg(Wp2 + p);
        wv += __shfl_xor_sync(0xffffffffu, wv, 1);
        wv += __shfl_xor_sync(0xffffffffu, wv, 2);
        wv += __shfl_xor_sync(0xffffffffu, wv, 4);
        wv += __shfl_xor_sync(0xffffffffu, wv, 8);
        if (p == 0) sw[pn][pg] = wv;
    }
    __syncthreads();

    int on = tid >> 6, f = tid & 63;
    float w0 = sw[on][0], w1 = sw[on][1];
    float mm = fmaxf(w0, w1);
    float b0 = __expf(w0 - mm), b1 = __expf(w1 - mm);
    float ib = 1.f / (b0 + b1);
    int oi = blockIdx.x * 4 + on;
    out[(size_t)oi * 64 + f] = (b0 * se[on][0][f] + b1 * se[on][1][f]) * ib;
}

// ---------------- launch ----------------
extern "C" void kernel_launch(void* const* d_in, const int* in_sizes, int n_in,
                              void* d_out, int out_size) {
    const float* x    = (const float*)d_in[0];
    const float* sadj = (const float*)d_in[1];
    const float* sadj2= (const float*)d_in[2];
    const float* W1   = (const float*)d_in[3];
    const float* a1   = (const float*)d_in[4];
    const float* Wo1  = (const float*)d_in[5];
    const float* ao1  = (const float*)d_in[6];
    const float* W2   = (const float*)d_in[7];
    const float* a2   = (const float*)d_in[8];
    const float* Wo2  = (const float*)d_in[9];
    const float* ao2  = (const float*)d_in[10];
    const float* Wp1  = (const float*)d_in[11];
    const float* bp1  = (const float*)d_in[12];
    const float* Wp2  = (const float*)d_in[13];
    float* out = (float*)d_out;

    static cudaStream_t s_side = nullptr;
    static cudaEvent_t  ev_fork = nullptr, ev_join = nullptr;
    if (!s_side) {
        cudaStreamCreateWithFlags(&s_side, cudaStreamNonBlocking);
        cudaEventCreateWithFlags(&ev_fork, cudaEventDisableTiming);
        cudaEventCreateWithFlags(&ev_join, cudaEventDisableTiming);
    }

    cudaEventRecord(ev_fork, 0);
    cudaStreamWaitEvent(s_side, ev_fork, 0);
    csr_build<<<1024, 256, 0, s_side>>>(sadj, sadj2);
    cudaEventRecord(ev_join, s_side);

    gemm1<<<dim3(32, 8), 256>>>(x, W1, W2, a1, a2);

    cudaStreamWaitEvent(0, ev_join, 0);

    attn_layer1<<<1024, 256>>>();
    gemm2f<<<dim3(128, 2), 256>>>(Wo1, Wo2, ao1, ao2);
    attn2_final<<<1024, 256>>>(Wp1, bp1, Wp2, out);
}

// round 14
// speedup vs baseline: 1.2452x; 1.2452x over previous
#include <cuda_runtime.h>
#include <cuda_bf16.h>
#include <math.h>
#include <stdint.h>

#define N_NODES 4096
#define FIN     256
#define NHEAD   4
#define FHID    64
#define FFIN    64
#define NPROJ   16
#define MAXD    128

// ---------------- scratch ----------------
__device__ int   g_cols[2][N_NODES][MAXD];
__device__ int   g_deg [2][N_NODES];
__device__ float g_Wh  [N_NODES][512];      // x @ Wcat   (cols: g*256 + h*64 + f)
__device__ float g_s1t [2][N_NODES][4];
__device__ float g_s2t [2][N_NODES][4];
__device__ float g_hcat[2][N_NODES][256];
__device__ float g_Wh2 [2][N_NODES][64];
__device__ float g_s1o [2][N_NODES];
__device__ float g_s2o [2][N_NODES];
// fragment-packed split-bf16 operands for mma.sync gemm1
// A2[mb][kc][lane] : uint4 = regs {a0,a1,a2,a3} for m16 block mb, k16 chunk kc
__device__ uint4 g_A2[256 * 48 * 32];
// B2[by*4+p][kc][lane] : uint4 = {b0(j),b1(j),b0(j+1),b1(j+1)} for n-tile pair p
__device__ uint4 g_B2[32 * 48 * 32];

__device__ __forceinline__ float lkexp(float z) {
    z = z >= 0.f ? z : 0.2f * z;
    return __expf(z);
}
__device__ __forceinline__ float elu1(float v) {
    return v > 0.f ? v : (__expf(v) - 1.f);
}

// pack two floats as bf16x2 (hi part or lo residual part)
__device__ __forceinline__ uint32_t pack2(float v0, float v1, int lo_part) {
    __nv_bfloat16 h0 = __float2bfloat16(v0);
    __nv_bfloat16 h1 = __float2bfloat16(v1);
    if (lo_part) {
        h0 = __float2bfloat16(v0 - __bfloat162float(h0));
        h1 = __float2bfloat16(v1 - __bfloat162float(h1));
    }
    uint32_t u0, u1;
    u0 = (uint32_t)*(uint16_t*)&h0;
    u1 = (uint32_t)*(uint16_t*)&h1;
    return u0 | (u1 << 16);
}

__device__ __forceinline__ void mma_bf16(float* d,
        uint32_t a0, uint32_t a1, uint32_t a2, uint32_t a3,
        uint32_t b0, uint32_t b1) {
    asm volatile(
        "mma.sync.aligned.m16n8k16.row.col.f32.bf16.bf16.f32 "
        "{%0,%1,%2,%3}, {%4,%5,%6,%7}, {%8,%9}, {%0,%1,%2,%3};"
        : "+f"(d[0]), "+f"(d[1]), "+f"(d[2]), "+f"(d[3])
        : "r"(a0), "r"(a1), "r"(a2), "r"(a3), "r"(b0), "r"(b1));
}

// =====================================================================
// CSR build (round-11 proven)
// =====================================================================
__device__ __forceinline__ void place_bits(unsigned nb, int cb, int& pos, int* __restrict__ row) {
    while (nb) {
        int b = __ffs(nb) - 1;
        nb &= nb - 1;
        if (pos < MAXD) row[pos] = cb + b;
        pos++;
    }
}

__global__ void csr_build(const float* __restrict__ m0, const float* __restrict__ m1) {
    int tid  = threadIdx.x;
    int w    = blockIdx.x * 8 + (tid >> 5);
    int lane = tid & 31;
    int g = w >> 12, r = w & 4095;
    const float4* mask = (const float4*)((g ? m1 : m0) + (size_t)r * N_NODES);
    int* row = &g_cols[g][r][0];
    int cnt = 0;
    for (int jb = 0; jb < 1024; jb += 128) {
        float4 v0 = mask[jb + lane];
        float4 v1 = mask[jb + 32 + lane];
        float4 v2 = mask[jb + 64 + lane];
        float4 v3 = mask[jb + 96 + lane];
        unsigned n0 = (v0.x > 0.f) | ((v0.y > 0.f) << 1) | ((v0.z > 0.f) << 2) | ((v0.w > 0.f) << 3);
        unsigned n1 = (v1.x > 0.f) | ((v1.y > 0.f) << 1) | ((v1.z > 0.f) << 2) | ((v1.w > 0.f) << 3);
        unsigned n2 = (v2.x > 0.f) | ((v2.y > 0.f) << 1) | ((v2.z > 0.f) << 2) | ((v2.w > 0.f) << 3);
        unsigned n3 = (v3.x > 0.f) | ((v3.y > 0.f) << 1) | ((v3.z > 0.f) << 2) | ((v3.w > 0.f) << 3);
        int c = __popc(n0) + __popc(n1) + __popc(n2) + __popc(n3);
        int s = c;
        #pragma unroll
        for (int off = 1; off < 32; off <<= 1) {
            int t = __shfl_up_sync(0xffffffffu, s, off);
            if (lane >= off) s += t;
        }
        int pos = cnt + s - c;
        cnt += __shfl_sync(0xffffffffu, s, 31);
        if (c) {
            place_bits(n0, (jb + lane) * 4,      pos, row);
            place_bits(n1, (jb + 32 + lane) * 4, pos, row);
            place_bits(n2, (jb + 64 + lane) * 4, pos, row);
            place_bits(n3, (jb + 96 + lane) * 4, pos, row);
        }
    }
    if (lane == 0) g_deg[g][r] = cnt < MAXD ? cnt : MAXD;
}

// =====================================================================
// prep_x2: x -> fragment-packed split A'.  A'[m][k'] with k' regions
// [0,256)=hi, [256,512)=lo, [512,768)=hi.  393216 threads.
// =====================================================================
__global__ void prep_x2(const float* __restrict__ x) {
    int idx = blockIdx.x * 256 + threadIdx.x;
    int lane = idx & 31;
    int kc   = (idx >> 5) % 48;
    int mb   = idx / (48 * 32);
    int g = lane >> 2, tq = lane & 3;
    int row0 = mb * 16 + g, row1 = row0 + 8;
    int c0 = kc * 16 + 2 * tq;       // k' of a0 pair
    int c1 = c0 + 8;                 // k' of a2 pair
    // region decode
    int s0 = c0 < 256 ? c0 : (c0 < 512 ? c0 - 256 : c0 - 512);
    int l0 = (c0 >= 256 && c0 < 512);
    int s1 = c1 < 256 ? c1 : (c1 < 512 ? c1 - 256 : c1 - 512);
    int l1 = (c1 >= 256 && c1 < 512);
    float2 v00 = *(const float2*)(x + (size_t)row0 * FIN + s0);
    float2 v10 = *(const float2*)(x + (size_t)row1 * FIN + s0);
    float2 v01 = *(const float2*)(x + (size_t)row0 * FIN + s1);
    float2 v11 = *(const float2*)(x + (size_t)row1 * FIN + s1);
    uint4 o;
    o.x = pack2(v00.x, v00.y, l0);   // a0: row g,   k c0
    o.y = pack2(v10.x, v10.y, l0);   // a1: row g+8, k c0
    o.z = pack2(v01.x, v01.y, l1);   // a2: row g,   k c1
    o.w = pack2(v11.x, v11.y, l1);   // a3: row g+8, k c1
    g_A2[((size_t)mb * 48 + kc) * 32 + lane] = o;
}

// =====================================================================
// prep_w2: W -> fragment-packed split B'.  B'[n][k'] regions
// [0,512)=hi (dup), [512,768)=lo.  49152 threads.
// =====================================================================
__global__ void prep_w2(const float* __restrict__ W1, const float* __restrict__ W2) {
    int idx = blockIdx.x * 256 + threadIdx.x;
    int lane = idx & 31;
    int kc   = (idx >> 5) % 48;
    int pp   = idx / (48 * 32);      // 0..31 = by*4 + p
    int by = pp >> 2, p = pp & 3;
    int gsel = by >> 2, h = by & 3;
    const float* W = (gsel ? W2 : W1) + (size_t)h * FIN * FHID;   // [256][64]
    int g = lane >> 2, tq = lane & 3;
    int n_a = 16 * p + g, n_b = n_a + 8;
    int r0 = kc * 16 + 2 * tq;
    int r1 = r0 + 8;
    int s0 = r0 < 512 ? (r0 & 255) : (r0 - 512);
    int l0 = (r0 >= 512);
    int s1 = r1 < 512 ? (r1 & 255) : (r1 - 512);
    int l1 = (r1 >= 512);
    // b0(j) = {B[r0][n], B[r0+1][n]}  -> W[s0][n], W[s0+1][n]
    uint4 o;
    o.x = pack2(W[(size_t)s0 * 64 + n_a], W[(size_t)(s0 + 1) * 64 + n_a], l0);
    o.y = pack2(W[(size_t)s1 * 64 + n_a], W[(size_t)(s1 + 1) * 64 + n_a], l1);
    o.z = pack2(W[(size_t)s0 * 64 + n_b], W[(size_t)(s0 + 1) * 64 + n_b], l0);
    o.w = pack2(W[(size_t)s1 * 64 + n_b], W[(size_t)(s1 + 1) * 64 + n_b], l1);
    g_B2[((size_t)pp * 48 + kc) * 32 + lane] = o;
}

// =====================================================================
// GEMM1 via mma.sync bf16 split: D[4096,512] = A'[4096,768] @ B'^T.
// grid (32, 8), 256 threads = 8 warps; warp = 16m x 64n, 48 k-steps.
// + s1/s2 epilogue from fragments.
// =====================================================================
__global__ void __launch_bounds__(256) gemm1_mma(
        const float* __restrict__ a1, const float* __restrict__ a2) {
    int tid = threadIdx.x;
    int wm = tid >> 5, lane = tid & 31;
    int g = lane >> 2, tq = lane & 3;
    int bx = blockIdx.x, by = blockIdx.y;
    int gsel = by >> 2, h = by & 3;
    int mb = bx * 8 + wm;

    const uint4* Abase = &g_A2[(size_t)mb * 48 * 32 + lane];
    const uint4* Bbase0 = &g_B2[((size_t)(by * 4 + 0) * 48) * 32 + lane];
    const uint4* Bbase1 = &g_B2[((size_t)(by * 4 + 1) * 48) * 32 + lane];
    const uint4* Bbase2 = &g_B2[((size_t)(by * 4 + 2) * 48) * 32 + lane];
    const uint4* Bbase3 = &g_B2[((size_t)(by * 4 + 3) * 48) * 32 + lane];

    float acc[8][4] = {};
    #pragma unroll 4
    for (int kc = 0; kc < 48; kc++) {
        uint4 A  = Abase [kc * 32];
        uint4 B0 = Bbase0[kc * 32];
        uint4 B1 = Bbase1[kc * 32];
        uint4 B2 = Bbase2[kc * 32];
        uint4 B3 = Bbase3[kc * 32];
        mma_bf16(acc[0], A.x, A.y, A.z, A.w, B0.x, B0.y);
        mma_bf16(acc[1], A.x, A.y, A.z, A.w, B0.z, B0.w);
        mma_bf16(acc[2], A.x, A.y, A.z, A.w, B1.x, B1.y);
        mma_bf16(acc[3], A.x, A.y, A.z, A.w, B1.z, B1.w);
        mma_bf16(acc[4], A.x, A.y, A.z, A.w, B2.x, B2.y);
        mma_bf16(acc[5], A.x, A.y, A.z, A.w, B2.z, B2.w);
        mma_bf16(acc[6], A.x, A.y, A.z, A.w, B3.x, B3.y);
        mma_bf16(acc[7], A.x, A.y, A.z, A.w, B3.z, B3.w);
    }

    // D layout per thread: acc[jt] = {D[g][jt*8+2tq], D[g][+1], D[g+8][jt*8+2tq], [+1]}
    int gm0 = bx * 128 + wm * 16 + g;
    int gm1 = gm0 + 8;
    int n0 = by * 64;
    #pragma unroll
    for (int jt = 0; jt < 8; jt++) {
        int c = n0 + jt * 8 + 2 * tq;
        *(float2*)&g_Wh[gm0][c] = make_float2(acc[jt][0], acc[jt][1]);
        *(float2*)&g_Wh[gm1][c] = make_float2(acc[jt][2], acc[jt][3]);
    }
    // s1/s2 epilogue
    const float* av = (gsel ? a2 : a1) + h * 128;
    float s1r0 = 0.f, s2r0 = 0.f, s1r1 = 0.f, s2r1 = 0.f;
    #pragma unroll
    for (int jt = 0; jt < 8; jt++) {
        int c = jt * 8 + 2 * tq;
        float av0 = __ldg(av + c),      av1 = __ldg(av + c + 1);
        float ad0 = __ldg(av + 64 + c), ad1 = __ldg(av + 64 + c + 1);
        s1r0 += acc[jt][0] * av0 + acc[jt][1] * av1;
        s2r0 += acc[jt][0] * ad0 + acc[jt][1] * ad1;
        s1r1 += acc[jt][2] * av0 + acc[jt][3] * av1;
        s2r1 += acc[jt][2] * ad0 + acc[jt][3] * ad1;
    }
    #pragma unroll
    for (int off = 1; off < 4; off <<= 1) {
        s1r0 += __shfl_xor_sync(0xffffffffu, s1r0, off);
        s2r0 += __shfl_xor_sync(0xffffffffu, s2r0, off);
        s1r1 += __shfl_xor_sync(0xffffffffu, s1r1, off);
        s2r1 += __shfl_xor_sync(0xffffffffu, s2r1, off);
    }
    if (tq == 0) {
        g_s1t[gsel][gm0][h] = s1r0;
        g_s2t[gsel][gm0][h] = s2r0;
        g_s1t[gsel][gm1][h] = s1r1;
        g_s2t[gsel][gm1][h] = s2r1;
    }
}

// ---- 4-head gather chunk (attn1) ----
__device__ __forceinline__ void gat_chunk1(const float* __restrict__ tab, int lim,
                                           int cj, float4 ej,
                                           float& ax0, float& ay0, float& ax1, float& ay1,
                                           float& ax2, float& ay2, float& ax3, float& ay3) {
    int kk = 0;
    for (; kk + 2 <= lim; kk += 2) {
        int   ca  = __shfl_sync(0xffffffffu, cj, kk);
        int   cb  = __shfl_sync(0xffffffffu, cj, kk + 1);
        float ea0 = __shfl_sync(0xffffffffu, ej.x, kk);
        float ea1 = __shfl_sync(0xffffffffu, ej.y, kk);
        float ea2 = __shfl_sync(0xffffffffu, ej.z, kk);
        float ea3 = __shfl_sync(0xffffffffu, ej.w, kk);
        float eb0 = __shfl_sync(0xffffffffu, ej.x, kk + 1);
        float eb1 = __shfl_sync(0xffffffffu, ej.y, kk + 1);
        float eb2 = __shfl_sync(0xffffffffu, ej.z, kk + 1);
        float eb3 = __shfl_sync(0xffffffffu, ej.w, kk + 1);
        const float* ra = tab + (size_t)ca * 512;
        const float* rb = tab + (size_t)cb * 512;
        float2 va0 = *(const float2*)(ra);
        float2 va1 = *(const float2*)(ra + 64);
        float2 va2 = *(const float2*)(ra + 128);
        float2 va3 = *(const float2*)(ra + 192);
        float2 vb0 = *(const float2*)(rb);
        float2 vb1 = *(const float2*)(rb + 64);
        float2 vb2 = *(const float2*)(rb + 128);
        float2 vb3 = *(const float2*)(rb + 192);
        ax0 += ea0 * va0.x + eb0 * vb0.x;  ay0 += ea0 * va0.y + eb0 * vb0.y;
        ax1 += ea1 * va1.x + eb1 * vb1.x;  ay1 += ea1 * va1.y + eb1 * vb1.y;
        ax2 += ea2 * va2.x + eb2 * vb2.x;  ay2 += ea2 * va2.y + eb2 * vb2.y;
        ax3 += ea3 * va3.x + eb3 * vb3.x;  ay3 += ea3 * va3.y + eb3 * vb3.y;
    }
    if (kk < lim) {
        int   ca  = __shfl_sync(0xffffffffu, cj, kk);
        float ea0 = __shfl_sync(0xffffffffu, ej.x, kk);
        float ea1 = __shfl_sync(0xffffffffu, ej.y, kk);
        float ea2 = __shfl_sync(0xffffffffu, ej.z, kk);
        float ea3 = __shfl_sync(0xffffffffu, ej.w, kk);
        const float* ra = tab + (size_t)ca * 512;
        float2 va0 = *(const float2*)(ra);
        float2 va1 = *(const float2*)(ra + 64);
        float2 va2 = *(const float2*)(ra + 128);
        float2 va3 = *(const float2*)(ra + 192);
        ax0 += ea0 * va0.x;  ay0 += ea0 * va0.y;
        ax1 += ea1 * va1.x;  ay1 += ea1 * va1.y;
        ax2 += ea2 * va2.x;  ay2 += ea2 * va2.y;
        ax3 += ea3 * va3.x;  ay3 += ea3 * va3.y;
    }
}

// =====================================================================
// Layer-1 attention (round-11 proven)
// =====================================================================
__global__ void attn_layer1() {
    int tid  = threadIdx.x;
    int lane = tid & 31;
    int w    = tid >> 5;
    int n    = w >> 1;
    int g    = w & 1;
    int i    = blockIdx.x * 4 + n;

    int d = g_deg[g][i];
    float4 s1 = *(const float4*)&g_s1t[g][i][0];

    int c0 = 0, c1 = 0;
    float4 e0 = make_float4(0.f, 0.f, 0.f, 0.f);
    float4 e1 = make_float4(0.f, 0.f, 0.f, 0.f);
    if (lane < d) {
        c0 = g_cols[g][i][lane];
        float4 s2 = *(const float4*)&g_s2t[g][c0][0];
        e0.x = lkexp(s1.x + s2.x);  e0.y = lkexp(s1.y + s2.y);
        e0.z = lkexp(s1.z + s2.z);  e0.w = lkexp(s1.w + s2.w);
    }
    if (lane + 32 < d) {
        c1 = g_cols[g][i][lane + 32];
        float4 s2 = *(const float4*)&g_s2t[g][c1][0];
        e1.x = lkexp(s1.x + s2.x);  e1.y = lkexp(s1.y + s2.y);
        e1.z = lkexp(s1.z + s2.z);  e1.w = lkexp(s1.w + s2.w);
    }
    float sx = e0.x + e1.x, sy = e0.y + e1.y, sz = e0.z + e1.z, sw = e0.w + e1.w;
    #pragma unroll
    for (int off = 16; off; off >>= 1) {
        sx += __shfl_xor_sync(0xffffffffu, sx, off);
        sy += __shfl_xor_sync(0xffffffffu, sy, off);
        sz += __shfl_xor_sync(0xffffffffu, sz, off);
        sw += __shfl_xor_sync(0xffffffffu, sw, off);
    }
    float ix = 1.f / sx, iy = 1.f / sy, iz = 1.f / sz, iw = 1.f / sw;

    const float* tab = &g_Wh[0][g * 256 + 2 * lane];
    float ax0 = 0.f, ay0 = 0.f, ax1 = 0.f, ay1 = 0.f;
    float ax2 = 0.f, ay2 = 0.f, ax3 = 0.f, ay3 = 0.f;
    int lim0 = d < 32 ? d : 32;
    int lim1 = d - 32; lim1 = lim1 < 0 ? 0 : lim1;
    gat_chunk1(tab, lim0, c0, e0, ax0, ay0, ax1, ay1, ax2, ay2, ax3, ay3);
    gat_chunk1(tab, lim1, c1, e1, ax0, ay0, ax1, ay1, ax2, ay2, ax3, ay3);

    float* orow = &g_hcat[g][i][2 * lane];
    float2 o;
    o.x = elu1(ax0 * ix);  o.y = elu1(ay0 * ix);  *(float2*)(orow)       = o;
    o.x = elu1(ax1 * iy);  o.y = elu1(ay1 * iy);  *(float2*)(orow + 64)  = o;
    o.x = elu1(ax2 * iz);  o.y = elu1(ay2 * iz);  *(float2*)(orow + 128) = o;
    o.x = elu1(ax3 * iw);  o.y = elu1(ay3 * iw);  *(float2*)(orow + 192) = o;
}

// =====================================================================
// GEMM2 (K-split, round-11 proven)
// =====================================================================
__global__ void __launch_bounds__(256) gemm2f(
        const float* __restrict__ Wo1, const float* __restrict__ Wo2,
        const float* __restrict__ ao1, const float* __restrict__ ao2) {
    __shared__ float As[2][2][16][36];
    __shared__ float Bs[2][2][16][64];
    __shared__ float red[32][64];
    int g = blockIdx.y;
    int m0r = blockIdx.x * 32;
    const float* A  = &g_hcat[g][0][0];
    const float* B  = g ? Wo2 : Wo1;
    const float* ao = g ? ao2 : ao1;
    int tid  = threadIdx.x;
    int kg   = tid >> 7;
    int tloc = tid & 127;
    int tx = tloc & 15, ty = tloc >> 4;
    int am = tloc >> 2, ak4 = tloc & 3;
    int bk0 = tloc >> 4, bc0 = (tloc & 15) * 4;
    int bk1 = (128 + tloc) >> 4, bc1 = ((128 + tloc) & 15) * 4;
    int kbase = kg * 128;
    const float* Aptr = A + (size_t)(m0r + am) * 256 + kbase;
    const float* Bptr = B + (size_t)kbase * 64;

    float4 fa  = *(const float4*)(Aptr + ak4 * 4);
    float4 fb0 = *(const float4*)(Bptr + (size_t)bk0 * 64 + bc0);
    float4 fb1 = *(const float4*)(Bptr + (size_t)bk1 * 64 + bc1);
    As[kg][0][ak4 * 4 + 0][am] = fa.x; As[kg][0][ak4 * 4 + 1][am] = fa.y;
    As[kg][0][ak4 * 4 + 2][am] = fa.z; As[kg][0][ak4 * 4 + 3][am] = fa.w;
    *(float4*)&Bs[kg][0][bk0][bc0] = fb0;
    *(float4*)&Bs[kg][0][bk1][bc1] = fb1;
    __syncthreads();

    float acc[4][4] = {};
    #pragma unroll
    for (int t = 0; t < 8; t++) {
        int cur = t & 1;
        if (t < 7) {
            int kb = (t + 1) * 16;
            fa  = *(const float4*)(Aptr + kb + ak4 * 4);
            fb0 = *(const float4*)(Bptr + (size_t)(kb + bk0) * 64 + bc0);
            fb1 = *(const float4*)(Bptr + (size_t)(kb + bk1) * 64 + bc1);
        }
        #pragma unroll
        for (int kk = 0; kk < 16; kk++) {
            float4 av = *(const float4*)&As[kg][cur][kk][ty * 4];
            float4 bv = *(const float4*)&Bs[kg][cur][kk][tx * 4];
            float a[4] = {av.x, av.y, av.z, av.w};
            float b[4] = {bv.x, bv.y, bv.z, bv.w};
            #pragma unroll
            for (int r = 0; r < 4; r++)
                #pragma unroll
                for (int c = 0; c < 4; c++)
                    acc[r][c] += a[r] * b[c];
        }
        if (t < 7) {
            int nxt = cur ^ 1;
            As[kg][nxt][ak4 * 4 + 0][am] = fa.x; As[kg][nxt][ak4 * 4 + 1][am] = fa.y;
            As[kg][nxt][ak4 * 4 + 2][am] = fa.z; As[kg][nxt][ak4 * 4 + 3][am] = fa.w;
            *(float4*)&Bs[kg][nxt][bk0][bc0] = fb0;
            *(float4*)&Bs[kg][nxt][bk1][bc1] = fb1;
        }
        __syncthreads();
    }

    if (kg == 1) {
        #pragma unroll
        for (int r = 0; r < 4; r++) {
            float4 v = make_float4(acc[r][0], acc[r][1], acc[r][2], acc[r][3]);
            *(float4*)&red[ty * 4 + r][tx * 4] = v;
        }
    }
    __syncthreads();
    if (kg == 0) {
        #pragma unroll
        for (int r = 0; r < 4; r++) {
            float4 v = *(const float4*)&red[ty * 4 + r][tx * 4];
            acc[r][0] += v.x; acc[r][1] += v.y; acc[r][2] += v.z; acc[r][3] += v.w;
        }
        #pragma unroll
        for (int r = 0; r < 4; r++) {
            int m = m0r + ty * 4 + r;
            float4 v = make_float4(acc[r][0], acc[r][1], acc[r][2], acc[r][3]);
            *(float4*)&g_Wh2[g][m][tx * 4] = v;
        }
        float a_s[4], a_d[4];
        #pragma unroll
        for (int c = 0; c < 4; c++) {
            a_s[c] = __ldg(ao + tx * 4 + c);
            a_d[c] = __ldg(ao + 64 + tx * 4 + c);
        }
        #pragma unroll
        for (int r = 0; r < 4; r++) {
            float s1 = 0.f, s2 = 0.f;
            #pragma unroll
            for (int c = 0; c < 4; c++) { s1 += acc[r][c] * a_s[c]; s2 += acc[r][c] * a_d[c]; }
            #pragma unroll
            for (int off = 1; off < 16; off <<= 1) {
                s1 += __shfl_xor_sync(0xffffffffu, s1, off);
                s2 += __shfl_xor_sync(0xffffffffu, s2, off);
            }
            if (tx == 0) {
                int m = m0r + ty * 4 + r;
                g_s1o[g][m] = s1;
                g_s2o[g][m] = s2;
            }
        }
    }
}

// ---- scalar gather chunk (attn2) ----
__device__ __forceinline__ void gat_chunk2(const float* __restrict__ tab, int lim,
                                           int cj, float ej, float& ax, float& ay) {
    int kk = 0;
    for (; kk + 4 <= lim; kk += 4) {
        int   c0 = __shfl_sync(0xffffffffu, cj, kk);
        int   c1 = __shfl_sync(0xffffffffu, cj, kk + 1);
        int   c2 = __shfl_sync(0xffffffffu, cj, kk + 2);
        int   c3 = __shfl_sync(0xffffffffu, cj, kk + 3);
        float e0 = __shfl_sync(0xffffffffu, ej, kk);
        float e1 = __shfl_sync(0xffffffffu, ej, kk + 1);
        float e2 = __shfl_sync(0xffffffffu, ej, kk + 2);
        float e3 = __shfl_sync(0xffffffffu, ej, kk + 3);
        float2 v0 = *(const float2*)(tab + (size_t)c0 * 64);
        float2 v1 = *(const float2*)(tab + (size_t)c1 * 64);
        float2 v2 = *(const float2*)(tab + (size_t)c2 * 64);
        float2 v3 = *(const float2*)(tab + (size_t)c3 * 64);
        ax += e0 * v0.x + e1 * v1.x + e2 * v2.x + e3 * v3.x;
        ay += e0 * v0.y + e1 * v1.y + e2 * v2.y + e3 * v3.y;
    }
    for (; kk < lim; kk++) {
        int   c = __shfl_sync(0xffffffffu, cj, kk);
        float e = __shfl_sync(0xffffffffu, ej, kk);
        float2 v = *(const float2*)(tab + (size_t)c * 64);
        ax += e * v.x;
        ay += e * v.y;
    }
}

// =====================================================================
// Layer-2 attention + ELU + semantic fusion (round-11 proven)
// =====================================================================
__global__ void attn2_final(const float* __restrict__ Wp1, const float* __restrict__ bp1,
                            const float* __restrict__ Wp2, float* __restrict__ out) {
    int tid  = threadIdx.x;
    int lane = tid & 31;
    int w    = tid >> 5;
    int n    = w >> 1;
    int g    = w & 1;
    int i    = blockIdx.x * 4 + n;

    __shared__ float se[4][2][64];
    __shared__ float sw[4][2];

    int d = g_deg[g][i];
    float s1v = g_s1o[g][i];
    int c0 = 0, c1 = 0;
    float e0 = 0.f, e1 = 0.f;
    if (lane < d) {
        c0 = g_cols[g][i][lane];
        e0 = lkexp(s1v + g_s2o[g][c0]);
    }
    if (lane + 32 < d) {
        c1 = g_cols[g][i][lane + 32];
        e1 = lkexp(s1v + g_s2o[g][c1]);
    }
    float sum = e0 + e1;
    #pragma unroll
    for (int off = 16; off; off >>= 1) sum += __shfl_xor_sync(0xffffffffu, sum, off);
    float inv = 1.f / sum;

    const float* tab = &g_Wh2[g][0][2 * lane];
    float ax = 0.f, ay = 0.f;
    int lim0 = d < 32 ? d : 32;
    int lim1 = d - 32; lim1 = lim1 < 0 ? 0 : lim1;
    gat_chunk2(tab, lim0, c0, e0, ax, ay);
    gat_chunk2(tab, lim1, c1, e1, ax, ay);

    ax *= inv; ay *= inv;
    se[n][g][2 * lane]     = elu1(ax);
    se[n][g][2 * lane + 1] = elu1(ay);
    __syncthreads();

    if (tid < 128) {
        int pn = tid >> 5, pg = (tid >> 4) & 1, p = tid & 15;
        float s = __ldg(bp1 + p);
        #pragma unroll
        for (int f = 0; f < 64; f++) s += se[pn][pg][f] * __ldg(Wp1 + f * NPROJ + p);
        float e2x = __expf(2.f * s);
        float t = __fdividef(e2x - 1.f, e2x + 1.f);
        float wv = t * __ldg(Wp2 + p);
        wv += __shfl_xor_sync(0xffffffffu, wv, 1);
        wv += __shfl_xor_sync(0xffffffffu, wv, 2);
        wv += __shfl_xor_sync(0xffffffffu, wv, 4);
        wv += __shfl_xor_sync(0xffffffffu, wv, 8);
        if (p == 0) sw[pn][pg] = wv;
    }
    __syncthreads();

    int on = tid >> 6, f = tid & 63;
    float w0 = sw[on][0], w1 = sw[on][1];
    float mm = fmaxf(w0, w1);
    float b0 = __expf(w0 - mm), b1 = __expf(w1 - mm);
    float ib = 1.f / (b0 + b1);
    int oi = blockIdx.x * 4 + on;
    out[(size_t)oi * 64 + f] = (b0 * se[on][0][f] + b1 * se[on][1][f]) * ib;
}

// ---------------- launch ----------------
extern "C" void kernel_launch(void* const* d_in, const int* in_sizes, int n_in,
                              void* d_out, int out_size) {
    const float* x    = (const float*)d_in[0];
    const float* sadj = (const float*)d_in[1];
    const float* sadj2= (const float*)d_in[2];
    const float* W1   = (const float*)d_in[3];
    const float* a1   = (const float*)d_in[4];
    const float* Wo1  = (const float*)d_in[5];
    const float* ao1  = (const float*)d_in[6];
    const float* W2   = (const float*)d_in[7];
    const float* a2   = (const float*)d_in[8];
    const float* Wo2  = (const float*)d_in[9];
    const float* ao2  = (const float*)d_in[10];
    const float* Wp1  = (const float*)d_in[11];
    const float* bp1  = (const float*)d_in[12];
    const float* Wp2  = (const float*)d_in[13];
    float* out = (float*)d_out;

    static cudaStream_t s_side = nullptr;
    static cudaEvent_t  ev_fork = nullptr, ev_join = nullptr;
    if (!s_side) {
        cudaStreamCreateWithFlags(&s_side, cudaStreamNonBlocking);
        cudaEventCreateWithFlags(&ev_fork, cudaEventDisableTiming);
        cudaEventCreateWithFlags(&ev_join, cudaEventDisableTiming);
    }

    cudaEventRecord(ev_fork, 0);
    cudaStreamWaitEvent(s_side, ev_fork, 0);
    csr_build<<<1024, 256, 0, s_side>>>(sadj, sadj2);
    cudaEventRecord(ev_join, s_side);

    prep_x2<<<1536, 256>>>(x);
    prep_w2<<<192, 256>>>(W1, W2);
    gemm1_mma<<<dim3(32, 8), 256>>>(a1, a2);

    cudaStreamWaitEvent(0, ev_join, 0);

    attn_layer1<<<1024, 256>>>();
    gemm2f<<<dim3(128, 2), 256>>>(Wo1, Wo2, ao1, ao2);
    attn2_final<<<1024, 256>>>(Wp1, bp1, Wp2, out);
}

// round 15
// speedup vs baseline: 1.3519x; 1.0857x over previous
#include <cuda_runtime.h>
#include <cuda_bf16.h>
#include <math.h>
#include <stdint.h>

#define N_NODES 4096
#define FIN     256
#define NHEAD   4
#define FHID    64
#define FFIN    64
#define NPROJ   16
#define MAXD    128

// ---------------- scratch ----------------
__device__ int   g_cols[2][N_NODES][MAXD];
__device__ int   g_deg [2][N_NODES];
__device__ float g_Wh  [N_NODES][512];      // x @ Wcat   (cols: g*256 + h*64 + f)
__device__ float g_s1t [2][N_NODES][4];
__device__ float g_s2t [2][N_NODES][4];
__device__ float g_hcat[2][N_NODES][256];
__device__ float g_Wh2 [2][N_NODES][64];
__device__ float g_s1o [2][N_NODES];
__device__ float g_s2o [2][N_NODES];
// fragment-packed split-bf16 operands for mma.sync gemm1
__device__ uint4 g_A2[256 * 48 * 32];
__device__ uint4 g_B2[32 * 48 * 32];

__device__ __forceinline__ float lkexp(float z) {
    z = z >= 0.f ? z : 0.2f * z;
    return __expf(z);
}
__device__ __forceinline__ float elu1(float v) {
    return v > 0.f ? v : (__expf(v) - 1.f);
}

__device__ __forceinline__ uint32_t pack2(float v0, float v1, int lo_part) {
    __nv_bfloat16 h0 = __float2bfloat16(v0);
    __nv_bfloat16 h1 = __float2bfloat16(v1);
    if (lo_part) {
        h0 = __float2bfloat16(v0 - __bfloat162float(h0));
        h1 = __float2bfloat16(v1 - __bfloat162float(h1));
    }
    uint32_t u0, u1;
    u0 = (uint32_t)*(uint16_t*)&h0;
    u1 = (uint32_t)*(uint16_t*)&h1;
    return u0 | (u1 << 16);
}

__device__ __forceinline__ void mma_bf16(float* d,
        uint32_t a0, uint32_t a1, uint32_t a2, uint32_t a3,
        uint32_t b0, uint32_t b1) {
    asm volatile(
        "mma.sync.aligned.m16n8k16.row.col.f32.bf16.bf16.f32 "
        "{%0,%1,%2,%3}, {%4,%5,%6,%7}, {%8,%9}, {%0,%1,%2,%3};"
        : "+f"(d[0]), "+f"(d[1]), "+f"(d[2]), "+f"(d[3])
        : "r"(a0), "r"(a1), "r"(a2), "r"(a3), "r"(b0), "r"(b1));
}

// =====================================================================
// CSR build (round-11 proven)
// =====================================================================
__device__ __forceinline__ void place_bits(unsigned nb, int cb, int& pos, int* __restrict__ row) {
    while (nb) {
        int b = __ffs(nb) - 1;
        nb &= nb - 1;
        if (pos < MAXD) row[pos] = cb + b;
        pos++;
    }
}

__global__ void csr_build(const float* __restrict__ m0, const float* __restrict__ m1) {
    int tid  = threadIdx.x;
    int w    = blockIdx.x * 8 + (tid >> 5);
    int lane = tid & 31;
    int g = w >> 12, r = w & 4095;
    const float4* mask = (const float4*)((g ? m1 : m0) + (size_t)r * N_NODES);
    int* row = &g_cols[g][r][0];
    int cnt = 0;
    for (int jb = 0; jb < 1024; jb += 128) {
        float4 v0 = mask[jb + lane];
        float4 v1 = mask[jb + 32 + lane];
        float4 v2 = mask[jb + 64 + lane];
        float4 v3 = mask[jb + 96 + lane];
        unsigned n0 = (v0.x > 0.f) | ((v0.y > 0.f) << 1) | ((v0.z > 0.f) << 2) | ((v0.w > 0.f) << 3);
        unsigned n1 = (v1.x > 0.f) | ((v1.y > 0.f) << 1) | ((v1.z > 0.f) << 2) | ((v1.w > 0.f) << 3);
        unsigned n2 = (v2.x > 0.f) | ((v2.y > 0.f) << 1) | ((v2.z > 0.f) << 2) | ((v2.w > 0.f) << 3);
        unsigned n3 = (v3.x > 0.f) | ((v3.y > 0.f) << 1) | ((v3.z > 0.f) << 2) | ((v3.w > 0.f) << 3);
        int c = __popc(n0) + __popc(n1) + __popc(n2) + __popc(n3);
        int s = c;
        #pragma unroll
        for (int off = 1; off < 32; off <<= 1) {
            int t = __shfl_up_sync(0xffffffffu, s, off);
            if (lane >= off) s += t;
        }
        int pos = cnt + s - c;
        cnt += __shfl_sync(0xffffffffu, s, 31);
        if (c) {
            place_bits(n0, (jb + lane) * 4,      pos, row);
            place_bits(n1, (jb + 32 + lane) * 4, pos, row);
            place_bits(n2, (jb + 64 + lane) * 4, pos, row);
            place_bits(n3, (jb + 96 + lane) * 4, pos, row);
        }
    }
    if (lane == 0) g_deg[g][r] = cnt < MAXD ? cnt : MAXD;
}

// =====================================================================
// prep_x2 / prep_w2 (round-14 proven)
// =====================================================================
__global__ void prep_x2(const float* __restrict__ x) {
    int idx = blockIdx.x * 256 + threadIdx.x;
    int lane = idx & 31;
    int kc   = (idx >> 5) % 48;
    int mb   = idx / (48 * 32);
    int g = lane >> 2, tq = lane & 3;
    int row0 = mb * 16 + g, row1 = row0 + 8;
    int c0 = kc * 16 + 2 * tq;
    int c1 = c0 + 8;
    int s0 = c0 < 256 ? c0 : (c0 < 512 ? c0 - 256 : c0 - 512);
    int l0 = (c0 >= 256 && c0 < 512);
    int s1 = c1 < 256 ? c1 : (c1 < 512 ? c1 - 256 : c1 - 512);
    int l1 = (c1 >= 256 && c1 < 512);
    float2 v00 = *(const float2*)(x + (size_t)row0 * FIN + s0);
    float2 v10 = *(const float2*)(x + (size_t)row1 * FIN + s0);
    float2 v01 = *(const float2*)(x + (size_t)row0 * FIN + s1);
    float2 v11 = *(const float2*)(x + (size_t)row1 * FIN + s1);
    uint4 o;
    o.x = pack2(v00.x, v00.y, l0);
    o.y = pack2(v10.x, v10.y, l0);
    o.z = pack2(v01.x, v01.y, l1);
    o.w = pack2(v11.x, v11.y, l1);
    g_A2[((size_t)mb * 48 + kc) * 32 + lane] = o;
}

__global__ void prep_w2(const float* __restrict__ W1, const float* __restrict__ W2) {
    int idx = blockIdx.x * 256 + threadIdx.x;
    int lane = idx & 31;
    int kc   = (idx >> 5) % 48;
    int pp   = idx / (48 * 32);
    int by = pp >> 2, p = pp & 3;
    int gsel = by >> 2, h = by & 3;
    const float* W = (gsel ? W2 : W1) + (size_t)h * FIN * FHID;
    int g = lane >> 2, tq = lane & 3;
    int n_a = 16 * p + g, n_b = n_a + 8;
    int r0 = kc * 16 + 2 * tq;
    int r1 = r0 + 8;
    int s0 = r0 < 512 ? (r0 & 255) : (r0 - 512);
    int l0 = (r0 >= 512);
    int s1 = r1 < 512 ? (r1 & 255) : (r1 - 512);
    int l1 = (r1 >= 512);
    uint4 o;
    o.x = pack2(W[(size_t)s0 * 64 + n_a], W[(size_t)(s0 + 1) * 64 + n_a], l0);
    o.y = pack2(W[(size_t)s1 * 64 + n_a], W[(size_t)(s1 + 1) * 64 + n_a], l1);
    o.z = pack2(W[(size_t)s0 * 64 + n_b], W[(size_t)(s0 + 1) * 64 + n_b], l0);
    o.w = pack2(W[(size_t)s1 * 64 + n_b], W[(size_t)(s1 + 1) * 64 + n_b], l1);
    g_B2[((size_t)pp * 48 + kc) * 32 + lane] = o;
}

// =====================================================================
// GEMM1 via mma.sync bf16 split — pipelined + K-split warp pairs.
// grid (64, 8), 256 threads = 4 pairs x 2 kg. Warp tile 16m x 64n,
// 24 k-steps per warp, depth-2 register pipeline, smem pair-reduce.
// =====================================================================
__global__ void __launch_bounds__(256) gemm1_mma(
        const float* __restrict__ a1, const float* __restrict__ a2) {
    __shared__ float red[4][16][68];
    int tid = threadIdx.x;
    int wm = tid >> 5, lane = tid & 31;
    int p  = wm >> 1, kg = wm & 1;
    int g = lane >> 2, tq = lane & 3;
    int bx = blockIdx.x, by = blockIdx.y;
    int gsel = by >> 2, h = by & 3;
    int mb = bx * 4 + p;

    const uint4* Ab  = &g_A2[(size_t)mb * 48 * 32 + lane];
    const uint4* Bb0 = &g_B2[((size_t)(by * 4 + 0) * 48) * 32 + lane];
    const uint4* Bb1 = &g_B2[((size_t)(by * 4 + 1) * 48) * 32 + lane];
    const uint4* Bb2 = &g_B2[((size_t)(by * 4 + 2) * 48) * 32 + lane];
    const uint4* Bb3 = &g_B2[((size_t)(by * 4 + 3) * 48) * 32 + lane];

    int kc0 = kg * 24;
    float acc[8][4] = {};
    uint4 As_[2], B0_[2], B1_[2], B2_[2], B3_[2];
    As_[0] = Ab [kc0 * 32];
    B0_[0] = Bb0[kc0 * 32];
    B1_[0] = Bb1[kc0 * 32];
    B2_[0] = Bb2[kc0 * 32];
    B3_[0] = Bb3[kc0 * 32];
    #pragma unroll
    for (int t = 0; t < 24; t++) {
        int cur = t & 1, nxt = cur ^ 1;
        if (t < 23) {
            int kc = kc0 + t + 1;
            As_[nxt] = Ab [kc * 32];
            B0_[nxt] = Bb0[kc * 32];
            B1_[nxt] = Bb1[kc * 32];
            B2_[nxt] = Bb2[kc * 32];
            B3_[nxt] = Bb3[kc * 32];
        }
        uint4 A  = As_[cur];
        uint4 B0 = B0_[cur], B1 = B1_[cur], B2 = B2_[cur], B3 = B3_[cur];
        mma_bf16(acc[0], A.x, A.y, A.z, A.w, B0.x, B0.y);
        mma_bf16(acc[1], A.x, A.y, A.z, A.w, B0.z, B0.w);
        mma_bf16(acc[2], A.x, A.y, A.z, A.w, B1.x, B1.y);
        mma_bf16(acc[3], A.x, A.y, A.z, A.w, B1.z, B1.w);
        mma_bf16(acc[4], A.x, A.y, A.z, A.w, B2.x, B2.y);
        mma_bf16(acc[5], A.x, A.y, A.z, A.w, B2.z, B2.w);
        mma_bf16(acc[6], A.x, A.y, A.z, A.w, B3.x, B3.y);
        mma_bf16(acc[7], A.x, A.y, A.z, A.w, B3.z, B3.w);
    }

    // kg=1 publishes partials; kg=0 reduces + epilogue
    if (kg == 1) {
        #pragma unroll
        for (int jt = 0; jt < 8; jt++) {
            int c = jt * 8 + 2 * tq;
            *(float2*)&red[p][g][c]     = make_float2(acc[jt][0], acc[jt][1]);
            *(float2*)&red[p][g + 8][c] = make_float2(acc[jt][2], acc[jt][3]);
        }
    }
    __syncthreads();
    if (kg != 0) return;

    #pragma unroll
    for (int jt = 0; jt < 8; jt++) {
        int c = jt * 8 + 2 * tq;
        float2 v0 = *(const float2*)&red[p][g][c];
        float2 v1 = *(const float2*)&red[p][g + 8][c];
        acc[jt][0] += v0.x; acc[jt][1] += v0.y;
        acc[jt][2] += v1.x; acc[jt][3] += v1.y;
    }

    int gm0 = bx * 64 + p * 16 + g;
    int gm1 = gm0 + 8;
    int n0 = by * 64;
    #pragma unroll
    for (int jt = 0; jt < 8; jt++) {
        int c = n0 + jt * 8 + 2 * tq;
        *(float2*)&g_Wh[gm0][c] = make_float2(acc[jt][0], acc[jt][1]);
        *(float2*)&g_Wh[gm1][c] = make_float2(acc[jt][2], acc[jt][3]);
    }
    const float* av = (gsel ? a2 : a1) + h * 128;
    float s1r0 = 0.f, s2r0 = 0.f, s1r1 = 0.f, s2r1 = 0.f;
    #pragma unroll
    for (int jt = 0; jt < 8; jt++) {
        int c = jt * 8 + 2 * tq;
        float av0 = __ldg(av + c),      av1 = __ldg(av + c + 1);
        float ad0 = __ldg(av + 64 + c), ad1 = __ldg(av + 64 + c + 1);
        s1r0 += acc[jt][0] * av0 + acc[jt][1] * av1;
        s2r0 += acc[jt][0] * ad0 + acc[jt][1] * ad1;
        s1r1 += acc[jt][2] * av0 + acc[jt][3] * av1;
        s2r1 += acc[jt][2] * ad0 + acc[jt][3] * ad1;
    }
    #pragma unroll
    for (int off = 1; off < 4; off <<= 1) {
        s1r0 += __shfl_xor_sync(0xffffffffu, s1r0, off);
        s2r0 += __shfl_xor_sync(0xffffffffu, s2r0, off);
        s1r1 += __shfl_xor_sync(0xffffffffu, s1r1, off);
        s2r1 += __shfl_xor_sync(0xffffffffu, s2r1, off);
    }
    if (tq == 0) {
        g_s1t[gsel][gm0][h] = s1r0;
        g_s2t[gsel][gm0][h] = s2r0;
        g_s1t[gsel][gm1][h] = s1r1;
        g_s2t[gsel][gm1][h] = s2r1;
    }
}

// ---- 4-head gather chunk (attn1) ----
__device__ __forceinline__ void gat_chunk1(const float* __restrict__ tab, int lim,
                                           int cj, float4 ej,
                                           float& ax0, float& ay0, float& ax1, float& ay1,
                                           float& ax2, float& ay2, float& ax3, float& ay3) {
    int kk = 0;
    for (; kk + 2 <= lim; kk += 2) {
        int   ca  = __shfl_sync(0xffffffffu, cj, kk);
        int   cb  = __shfl_sync(0xffffffffu, cj, kk + 1);
        float ea0 = __shfl_sync(0xffffffffu, ej.x, kk);
        float ea1 = __shfl_sync(0xffffffffu, ej.y, kk);
        float ea2 = __shfl_sync(0xffffffffu, ej.z, kk);
        float ea3 = __shfl_sync(0xffffffffu, ej.w, kk);
        float eb0 = __shfl_sync(0xffffffffu, ej.x, kk + 1);
        float eb1 = __shfl_sync(0xffffffffu, ej.y, kk + 1);
        float eb2 = __shfl_sync(0xffffffffu, ej.z, kk + 1);
        float eb3 = __shfl_sync(0xffffffffu, ej.w, kk + 1);
        const float* ra = tab + (size_t)ca * 512;
        const float* rb = tab + (size_t)cb * 512;
        float2 va0 = *(const float2*)(ra);
        float2 va1 = *(const float2*)(ra + 64);
        float2 va2 = *(const float2*)(ra + 128);
        float2 va3 = *(const float2*)(ra + 192);
        float2 vb0 = *(const float2*)(rb);
        float2 vb1 = *(const float2*)(rb + 64);
        float2 vb2 = *(const float2*)(rb + 128);
        float2 vb3 = *(const float2*)(rb + 192);
        ax0 += ea0 * va0.x + eb0 * vb0.x;  ay0 += ea0 * va0.y + eb0 * vb0.y;
        ax1 += ea1 * va1.x + eb1 * vb1.x;  ay1 += ea1 * va1.y + eb1 * vb1.y;
        ax2 += ea2 * va2.x + eb2 * vb2.x;  ay2 += ea2 * va2.y + eb2 * vb2.y;
        ax3 += ea3 * va3.x + eb3 * vb3.x;  ay3 += ea3 * va3.y + eb3 * vb3.y;
    }
    if (kk < lim) {
        int   ca  = __shfl_sync(0xffffffffu, cj, kk);
        float ea0 = __shfl_sync(0xffffffffu, ej.x, kk);
        float ea1 = __shfl_sync(0xffffffffu, ej.y, kk);
        float ea2 = __shfl_sync(0xffffffffu, ej.z, kk);
        float ea3 = __shfl_sync(0xffffffffu, ej.w, kk);
        const float* ra = tab + (size_t)ca * 512;
        float2 va0 = *(const float2*)(ra);
        float2 va1 = *(const float2*)(ra + 64);
        float2 va2 = *(const float2*)(ra + 128);
        float2 va3 = *(const float2*)(ra + 192);
        ax0 += ea0 * va0.x;  ay0 += ea0 * va0.y;
        ax1 += ea1 * va1.x;  ay1 += ea1 * va1.y;
        ax2 += ea2 * va2.x;  ay2 += ea2 * va2.y;
        ax3 += ea3 * va3.x;  ay3 += ea3 * va3.y;
    }
}

// =====================================================================
// Layer-1 attention (round-11 proven)
// =====================================================================
__global__ void attn_layer1() {
    int tid  = threadIdx.x;
    int lane = tid & 31;
    int w    = tid >> 5;
    int n    = w >> 1;
    int g    = w & 1;
    int i    = blockIdx.x * 4 + n;

    int d = g_deg[g][i];
    float4 s1 = *(const float4*)&g_s1t[g][i][0];

    int c0 = 0, c1 = 0;
    float4 e0 = make_float4(0.f, 0.f, 0.f, 0.f);
    float4 e1 = make_float4(0.f, 0.f, 0.f, 0.f);
    if (lane < d) {
        c0 = g_cols[g][i][lane];
        float4 s2 = *(const float4*)&g_s2t[g][c0][0];
        e0.x = lkexp(s1.x + s2.x);  e0.y = lkexp(s1.y + s2.y);
        e0.z = lkexp(s1.z + s2.z);  e0.w = lkexp(s1.w + s2.w);
    }
    if (lane + 32 < d) {
        c1 = g_cols[g][i][lane + 32];
        float4 s2 = *(const float4*)&g_s2t[g][c1][0];
        e1.x = lkexp(s1.x + s2.x);  e1.y = lkexp(s1.y + s2.y);
        e1.z = lkexp(s1.z + s2.z);  e1.w = lkexp(s1.w + s2.w);
    }
    float sx = e0.x + e1.x, sy = e0.y + e1.y, sz = e0.z + e1.z, sw = e0.w + e1.w;
    #pragma unroll
    for (int off = 16; off; off >>= 1) {
        sx += __shfl_xor_sync(0xffffffffu, sx, off);
        sy += __shfl_xor_sync(0xffffffffu, sy, off);
        sz += __shfl_xor_sync(0xffffffffu, sz, off);
        sw += __shfl_xor_sync(0xffffffffu, sw, off);
    }
    float ix = 1.f / sx, iy = 1.f / sy, iz = 1.f / sz, iw = 1.f / sw;

    const float* tab = &g_Wh[0][g * 256 + 2 * lane];
    float ax0 = 0.f, ay0 = 0.f, ax1 = 0.f, ay1 = 0.f;
    float ax2 = 0.f, ay2 = 0.f, ax3 = 0.f, ay3 = 0.f;
    int lim0 = d < 32 ? d : 32;
    int lim1 = d - 32; lim1 = lim1 < 0 ? 0 : lim1;
    gat_chunk1(tab, lim0, c0, e0, ax0, ay0, ax1, ay1, ax2, ay2, ax3, ay3);
    gat_chunk1(tab, lim1, c1, e1, ax0, ay0, ax1, ay1, ax2, ay2, ax3, ay3);

    float* orow = &g_hcat[g][i][2 * lane];
    float2 o;
    o.x = elu1(ax0 * ix);  o.y = elu1(ay0 * ix);  *(float2*)(orow)       = o;
    o.x = elu1(ax1 * iy);  o.y = elu1(ay1 * iy);  *(float2*)(orow + 64)  = o;
    o.x = elu1(ax2 * iz);  o.y = elu1(ay2 * iz);  *(float2*)(orow + 128) = o;
    o.x = elu1(ax3 * iw);  o.y = elu1(ay3 * iw);  *(float2*)(orow + 192) = o;
}

// =====================================================================
// GEMM2 (K-split, round-11 proven)
// =====================================================================
__global__ void __launch_bounds__(256) gemm2f(
        const float* __restrict__ Wo1, const float* __restrict__ Wo2,
        const float* __restrict__ ao1, const float* __restrict__ ao2) {
    __shared__ float As[2][2][16][36];
    __shared__ float Bs[2][2][16][64];
    __shared__ float red[32][64];
    int g = blockIdx.y;
    int m0r = blockIdx.x * 32;
    const float* A  = &g_hcat[g][0][0];
    const float* B  = g ? Wo2 : Wo1;
    const float* ao = g ? ao2 : ao1;
    int tid  = threadIdx.x;
    int kg   = tid >> 7;
    int tloc = tid & 127;
    int tx = tloc & 15, ty = tloc >> 4;
    int am = tloc >> 2, ak4 = tloc & 3;
    int bk0 = tloc >> 4, bc0 = (tloc & 15) * 4;
    int bk1 = (128 + tloc) >> 4, bc1 = ((128 + tloc) & 15) * 4;
    int kbase = kg * 128;
    const float* Aptr = A + (size_t)(m0r + am) * 256 + kbase;
    const float* Bptr = B + (size_t)kbase * 64;

    float4 fa  = *(const float4*)(Aptr + ak4 * 4);
    float4 fb0 = *(const float4*)(Bptr + (size_t)bk0 * 64 + bc0);
    float4 fb1 = *(const float4*)(Bptr + (size_t)bk1 * 64 + bc1);
    As[kg][0][ak4 * 4 + 0][am] = fa.x; As[kg][0][ak4 * 4 + 1][am] = fa.y;
    As[kg][0][ak4 * 4 + 2][am] = fa.z; As[kg][0][ak4 * 4 + 3][am] = fa.w;
    *(float4*)&Bs[kg][0][bk0][bc0] = fb0;
    *(float4*)&Bs[kg][0][bk1][bc1] = fb1;
    __syncthreads();

    float acc[4][4] = {};
    #pragma unroll
    for (int t = 0; t < 8; t++) {
        int cur = t & 1;
        if (t < 7) {
            int kb = (t + 1) * 16;
            fa  = *(const float4*)(Aptr + kb + ak4 * 4);
            fb0 = *(const float4*)(Bptr + (size_t)(kb + bk0) * 64 + bc0);
            fb1 = *(const float4*)(Bptr + (size_t)(kb + bk1) * 64 + bc1);
        }
        #pragma unroll
        for (int kk = 0; kk < 16; kk++) {
            float4 av = *(const float4*)&As[kg][cur][kk][ty * 4];
            float4 bv = *(const float4*)&Bs[kg][cur][kk][tx * 4];
            float a[4] = {av.x, av.y, av.z, av.w};
            float b[4] = {bv.x, bv.y, bv.z, bv.w};
            #pragma unroll
            for (int r = 0; r < 4; r++)
                #pragma unroll
                for (int c = 0; c < 4; c++)
                    acc[r][c] += a[r] * b[c];
        }
        if (t < 7) {
            int nxt = cur ^ 1;
            As[kg][nxt][ak4 * 4 + 0][am] = fa.x; As[kg][nxt][ak4 * 4 + 1][am] = fa.y;
            As[kg][nxt][ak4 * 4 + 2][am] = fa.z; As[kg][nxt][ak4 * 4 + 3][am] = fa.w;
            *(float4*)&Bs[kg][nxt][bk0][bc0] = fb0;
            *(float4*)&Bs[kg][nxt][bk1][bc1] = fb1;
        }
        __syncthreads();
    }

    if (kg == 1) {
        #pragma unroll
        for (int r = 0; r < 4; r++) {
            float4 v = make_float4(acc[r][0], acc[r][1], acc[r][2], acc[r][3]);
            *(float4*)&red[ty * 4 + r][tx * 4] = v;
        }
    }
    __syncthreads();
    if (kg == 0) {
        #pragma unroll
        for (int r = 0; r < 4; r++) {
            float4 v = *(const float4*)&red[ty * 4 + r][tx * 4];
            acc[r][0] += v.x; acc[r][1] += v.y; acc[r][2] += v.z; acc[r][3] += v.w;
        }
        #pragma unroll
        for (int r = 0; r < 4; r++) {
            int m = m0r + ty * 4 + r;
            float4 v = make_float4(acc[r][0], acc[r][1], acc[r][2], acc[r][3]);
            *(float4*)&g_Wh2[g][m][tx * 4] = v;
        }
        float a_s[4], a_d[4];
        #pragma unroll
        for (int c = 0; c < 4; c++) {
            a_s[c] = __ldg(ao + tx * 4 + c);
            a_d[c] = __ldg(ao + 64 + tx * 4 + c);
        }
        #pragma unroll
        for (int r = 0; r < 4; r++) {
            float s1 = 0.f, s2 = 0.f;
            #pragma unroll
            for (int c = 0; c < 4; c++) { s1 += acc[r][c] * a_s[c]; s2 += acc[r][c] * a_d[c]; }
            #pragma unroll
            for (int off = 1; off < 16; off <<= 1) {
                s1 += __shfl_xor_sync(0xffffffffu, s1, off);
                s2 += __shfl_xor_sync(0xffffffffu, s2, off);
            }
            if (tx == 0) {
                int m = m0r + ty * 4 + r;
                g_s1o[g][m] = s1;
                g_s2o[g][m] = s2;
            }
        }
    }
}

// ---- scalar gather chunk (attn2) ----
__device__ __forceinline__ void gat_chunk2(const float* __restrict__ tab, int lim,
                                           int cj, float ej, float& ax, float& ay) {
    int kk = 0;
    for (; kk + 4 <= lim; kk += 4) {
        int   c0 = __shfl_sync(0xffffffffu, cj, kk);
        int   c1 = __shfl_sync(0xffffffffu, cj, kk + 1);
        int   c2 = __shfl_sync(0xffffffffu, cj, kk + 2);
        int   c3 = __shfl_sync(0xffffffffu, cj, kk + 3);
        float e0 = __shfl_sync(0xffffffffu, ej, kk);
        float e1 = __shfl_sync(0xffffffffu, ej, kk + 1);
        float e2 = __shfl_sync(0xffffffffu, ej, kk + 2);
        float e3 = __shfl_sync(0xffffffffu, ej, kk + 3);
        float2 v0 = *(const float2*)(tab + (size_t)c0 * 64);
        float2 v1 = *(const float2*)(tab + (size_t)c1 * 64);
        float2 v2 = *(const float2*)(tab + (size_t)c2 * 64);
        float2 v3 = *(const float2*)(tab + (size_t)c3 * 64);
        ax += e0 * v0.x + e1 * v1.x + e2 * v2.x + e3 * v3.x;
        ay += e0 * v0.y + e1 * v1.y + e2 * v2.y + e3 * v3.y;
    }
    for (; kk < lim; kk++) {
        int   c = __shfl_sync(0xffffffffu, cj, kk);
        float e = __shfl_sync(0xffffffffu, ej, kk);
        float2 v = *(const float2*)(tab + (size_t)c * 64);
        ax += e * v.x;
        ay += e * v.y;
    }
}

// =====================================================================
// Layer-2 attention + ELU + semantic fusion (round-11 proven)
// =====================================================================
__global__ void attn2_final(const float* __restrict__ Wp1, const float* __restrict__ bp1,
                            const float* __restrict__ Wp2, float* __restrict__ out) {
    int tid  = threadIdx.x;
    int lane = tid & 31;
    int w    = tid >> 5;
    int n    = w >> 1;
    int g    = w & 1;
    int i    = blockIdx.x * 4 + n;

    __shared__ float se[4][2][64];
    __shared__ float sw[4][2];

    int d = g_deg[g][i];
    float s1v = g_s1o[g][i];
    int c0 = 0, c1 = 0;
    float e0 = 0.f, e1 = 0.f;
    if (lane < d) {
        c0 = g_cols[g][i][lane];
        e0 = lkexp(s1v + g_s2o[g][c0]);
    }
    if (lane + 32 < d) {
        c1 = g_cols[g][i][lane + 32];
        e1 = lkexp(s1v + g_s2o[g][c1]);
    }
    float sum = e0 + e1;
    #pragma unroll
    for (int off = 16; off; off >>= 1) sum += __shfl_xor_sync(0xffffffffu, sum, off);
    float inv = 1.f / sum;

    const float* tab = &g_Wh2[g][0][2 * lane];
    float ax = 0.f, ay = 0.f;
    int lim0 = d < 32 ? d : 32;
    int lim1 = d - 32; lim1 = lim1 < 0 ? 0 : lim1;
    gat_chunk2(tab, lim0, c0, e0, ax, ay);
    gat_chunk2(tab, lim1, c1, e1, ax, ay);

    ax *= inv; ay *= inv;
    se[n][g][2 * lane]     = elu1(ax);
    se[n][g][2 * lane + 1] = elu1(ay);
    __syncthreads();

    if (tid < 128) {
        int pn = tid >> 5, pg = (tid >> 4) & 1, p = tid & 15;
        float s = __ldg(bp1 + p);
        #pragma unroll
        for (int f = 0; f < 64; f++) s += se[pn][pg][f] * __ldg(Wp1 + f * NPROJ + p);
        float e2x = __expf(2.f * s);
        float t = __fdividef(e2x - 1.f, e2x + 1.f);
        float wv = t * __ldg(Wp2 + p);
        wv += __shfl_xor_sync(0xffffffffu, wv, 1);
        wv += __shfl_xor_sync(0xffffffffu, wv, 2);
        wv += __shfl_xor_sync(0xffffffffu, wv, 4);
        wv += __shfl_xor_sync(0xffffffffu, wv, 8);
        if (p == 0) sw[pn][pg] = wv;
    }
    __syncthreads();

    int on = tid >> 6, f = tid & 63;
    float w0 = sw[on][0], w1 = sw[on][1];
    float mm = fmaxf(w0, w1);
    float b0 = __expf(w0 - mm), b1 = __expf(w1 - mm);
    float ib = 1.f / (b0 + b1);
    int oi = blockIdx.x * 4 + on;
    out[(size_t)oi * 64 + f] = (b0 * se[on][0][f] + b1 * se[on][1][f]) * ib;
}

// ---------------- launch ----------------
extern "C" void kernel_launch(void* const* d_in, const int* in_sizes, int n_in,
                              void* d_out, int out_size) {
    const float* x    = (const float*)d_in[0];
    const float* sadj = (const float*)d_in[1];
    const float* sadj2= (const float*)d_in[2];
    const float* W1   = (const float*)d_in[3];
    const float* a1   = (const float*)d_in[4];
    const float* Wo1  = (const float*)d_in[5];
    const float* ao1  = (const float*)d_in[6];
    const float* W2   = (const float*)d_in[7];
    const float* a2   = (const float*)d_in[8];
    const float* Wo2  = (const float*)d_in[9];
    const float* ao2  = (const float*)d_in[10];
    const float* Wp1  = (const float*)d_in[11];
    const float* bp1  = (const float*)d_in[12];
    const float* Wp2  = (const float*)d_in[13];
    float* out = (float*)d_out;

    static cudaStream_t s_side = nullptr;
    static cudaEvent_t  ev_fork = nullptr, ev_join = nullptr;
    if (!s_side) {
        cudaStreamCreateWithFlags(&s_side, cudaStreamNonBlocking);
        cudaEventCreateWithFlags(&ev_fork, cudaEventDisableTiming);
        cudaEventCreateWithFlags(&ev_join, cudaEventDisableTiming);
    }

    cudaEventRecord(ev_fork, 0);
    cudaStreamWaitEvent(s_side, ev_fork, 0);
    csr_build<<<1024, 256, 0, s_side>>>(sadj, sadj2);
    cudaEventRecord(ev_join, s_side);

    prep_x2<<<1536, 256>>>(x);
    prep_w2<<<192, 256>>>(W1, W2);
    gemm1_mma<<<dim3(64, 8), 256>>>(a1, a2);

    cudaStreamWaitEvent(0, ev_join, 0);

    attn_layer1<<<1024, 256>>>();
    gemm2f<<<dim3(128, 2), 256>>>(Wo1, Wo2, ao1, ao2);
    attn2_final<<<1024, 256>>>(Wp1, bp1, Wp2, out);
}

// round 16
// speedup vs baseline: 1.3696x; 1.0131x over previous
#include <cuda_runtime.h>
#include <cuda_bf16.h>
#include <math.h>
#include <stdint.h>

#define N_NODES 4096
#define FIN     256
#define NHEAD   4
#define FHID    64
#define FFIN    64
#define NPROJ   16
#define MAXD    128

// ---------------- scratch ----------------
__device__ int   g_cols[2][N_NODES][MAXD];
__device__ int   g_deg [2][N_NODES];
__device__ float g_Wh  [N_NODES][512];
__device__ float g_s1t [2][N_NODES][4];
__device__ float g_s2t [2][N_NODES][4];
__device__ float g_hcat[2][N_NODES][256];
__device__ float g_Wh2 [2][N_NODES][64];
__device__ float g_s1o [2][N_NODES];
__device__ float g_s2o [2][N_NODES];
__device__ uint4 g_A2[256 * 48 * 32];
__device__ uint4 g_B2[32 * 48 * 32];
__device__ uint4 g_Bo[8 * 48 * 32];

__device__ __forceinline__ float lkexp(float z) {
    z = z >= 0.f ? z : 0.2f * z;
    return __expf(z);
}
__device__ __forceinline__ float elu1(float v) {
    return v > 0.f ? v : (__expf(v) - 1.f);
}

__device__ __forceinline__ uint32_t pack2(float v0, float v1, int lo_part) {
    __nv_bfloat16 h0 = __float2bfloat16(v0);
    __nv_bfloat16 h1 = __float2bfloat16(v1);
    if (lo_part) {
        h0 = __float2bfloat16(v0 - __bfloat162float(h0));
        h1 = __float2bfloat16(v1 - __bfloat162float(h1));
    }
    uint32_t u0, u1;
    u0 = (uint32_t)*(uint16_t*)&h0;
    u1 = (uint32_t)*(uint16_t*)&h1;
    return u0 | (u1 << 16);
}

__device__ __forceinline__ void mma_bf16(float* d,
        uint32_t a0, uint32_t a1, uint32_t a2, uint32_t a3,
        uint32_t b0, uint32_t b1) {
    asm volatile(
        "mma.sync.aligned.m16n8k16.row.col.f32.bf16.bf16.f32 "
        "{%0,%1,%2,%3}, {%4,%5,%6,%7}, {%8,%9}, {%0,%1,%2,%3};"
        : "+f"(d[0]), "+f"(d[1]), "+f"(d[2]), "+f"(d[3])
        : "r"(a0), "r"(a1), "r"(a2), "r"(a3), "r"(b0), "r"(b1));
}

// =====================================================================
// CSR build (round-11 proven)
// =====================================================================
__device__ __forceinline__ void place_bits(unsigned nb, int cb, int& pos, int* __restrict__ row) {
    while (nb) {
        int b = __ffs(nb) - 1;
        nb &= nb - 1;
        if (pos < MAXD) row[pos] = cb + b;
        pos++;
    }
}

__global__ void csr_build(const float* __restrict__ m0, const float* __restrict__ m1) {
    int tid  = threadIdx.x;
    int w    = blockIdx.x * 8 + (tid >> 5);
    int lane = tid & 31;
    int g = w >> 12, r = w & 4095;
    const float4* mask = (const float4*)((g ? m1 : m0) + (size_t)r * N_NODES);
    int* row = &g_cols[g][r][0];
    int cnt = 0;
    for (int jb = 0; jb < 1024; jb += 128) {
        float4 v0 = mask[jb + lane];
        float4 v1 = mask[jb + 32 + lane];
        float4 v2 = mask[jb + 64 + lane];
        float4 v3 = mask[jb + 96 + lane];
        unsigned n0 = (v0.x > 0.f) | ((v0.y > 0.f) << 1) | ((v0.z > 0.f) << 2) | ((v0.w > 0.f) << 3);
        unsigned n1 = (v1.x > 0.f) | ((v1.y > 0.f) << 1) | ((v1.z > 0.f) << 2) | ((v1.w > 0.f) << 3);
        unsigned n2 = (v2.x > 0.f) | ((v2.y > 0.f) << 1) | ((v2.z > 0.f) << 2) | ((v2.w > 0.f) << 3);
        unsigned n3 = (v3.x > 0.f) | ((v3.y > 0.f) << 1) | ((v3.z > 0.f) << 2) | ((v3.w > 0.f) << 3);
        int c = __popc(n0) + __popc(n1) + __popc(n2) + __popc(n3);
        int s = c;
        #pragma unroll
        for (int off = 1; off < 32; off <<= 1) {
            int t = __shfl_up_sync(0xffffffffu, s, off);
            if (lane >= off) s += t;
        }
        int pos = cnt + s - c;
        cnt += __shfl_sync(0xffffffffu, s, 31);
        if (c) {
            place_bits(n0, (jb + lane) * 4,      pos, row);
            place_bits(n1, (jb + 32 + lane) * 4, pos, row);
            place_bits(n2, (jb + 64 + lane) * 4, pos, row);
            place_bits(n3, (jb + 96 + lane) * 4, pos, row);
        }
    }
    if (lane == 0) g_deg[g][r] = cnt < MAXD ? cnt : MAXD;
}

// =====================================================================
// prep_all: merged operand packing. blocks [0,1536)=x, [1536,1728)=W,
// [1728,1776)=Wo.
// =====================================================================
__global__ void prep_all(const float* __restrict__ x,
                         const float* __restrict__ W1, const float* __restrict__ W2,
                         const float* __restrict__ Wo1, const float* __restrict__ Wo2) {
    int bid = blockIdx.x;
    if (bid < 1536) {
        int idx = bid * 256 + threadIdx.x;
        int lane = idx & 31;
        int kc   = (idx >> 5) % 48;
        int mb   = idx / (48 * 32);
        int gl = lane >> 2, tq = lane & 3;
        int row0 = mb * 16 + gl, row1 = row0 + 8;
        int c0 = kc * 16 + 2 * tq;
        int c1 = c0 + 8;
        int s0 = c0 < 256 ? c0 : (c0 < 512 ? c0 - 256 : c0 - 512);
        int l0 = (c0 >= 256 && c0 < 512);
        int s1 = c1 < 256 ? c1 : (c1 < 512 ? c1 - 256 : c1 - 512);
        int l1 = (c1 >= 256 && c1 < 512);
        float2 v00 = *(const float2*)(x + (size_t)row0 * FIN + s0);
        float2 v10 = *(const float2*)(x + (size_t)row1 * FIN + s0);
        float2 v01 = *(const float2*)(x + (size_t)row0 * FIN + s1);
        float2 v11 = *(const float2*)(x + (size_t)row1 * FIN + s1);
        uint4 o;
        o.x = pack2(v00.x, v00.y, l0);
        o.y = pack2(v10.x, v10.y, l0);
        o.z = pack2(v01.x, v01.y, l1);
        o.w = pack2(v11.x, v11.y, l1);
        g_A2[((size_t)mb * 48 + kc) * 32 + lane] = o;
    } else if (bid < 1728) {
        int idx = (bid - 1536) * 256 + threadIdx.x;
        int lane = idx & 31;
        int kc   = (idx >> 5) % 48;
        int pp   = idx / (48 * 32);
        int by = pp >> 2, p = pp & 3;
        int gsel = by >> 2, h = by & 3;
        const float* W = (gsel ? W2 : W1) + (size_t)h * FIN * FHID;
        int gl = lane >> 2, tq = lane & 3;
        int n_a = 16 * p + gl, n_b = n_a + 8;
        int r0 = kc * 16 + 2 * tq;
        int r1 = r0 + 8;
        int s0 = r0 < 512 ? (r0 & 255) : (r0 - 512);
        int l0 = (r0 >= 512);
        int s1 = r1 < 512 ? (r1 & 255) : (r1 - 512);
        int l1 = (r1 >= 512);
        uint4 o;
        o.x = pack2(W[(size_t)s0 * 64 + n_a], W[(size_t)(s0 + 1) * 64 + n_a], l0);
        o.y = pack2(W[(size_t)s1 * 64 + n_a], W[(size_t)(s1 + 1) * 64 + n_a], l1);
        o.z = pack2(W[(size_t)s0 * 64 + n_b], W[(size_t)(s0 + 1) * 64 + n_b], l0);
        o.w = pack2(W[(size_t)s1 * 64 + n_b], W[(size_t)(s1 + 1) * 64 + n_b], l1);
        g_B2[((size_t)pp * 48 + kc) * 32 + lane] = o;
    } else {
        int idx = (bid - 1728) * 256 + threadIdx.x;     // [0, 12288)
        int lane = idx & 31;
        int kc   = (idx >> 5) % 48;
        int pp   = idx / (48 * 32);                     // 0..7 = g*4+p
        int g2 = pp >> 2, p = pp & 3;
        const float* W = g2 ? Wo2 : Wo1;                // [256][64]
        int gl = lane >> 2, tq = lane & 3;
        int n_a = 16 * p + gl, n_b = n_a + 8;
        int r0 = kc * 16 + 2 * tq;
        int r1 = r0 + 8;
        int s0 = r0 < 512 ? (r0 & 255) : (r0 - 512);
        int l0 = (r0 >= 512);
        int s1 = r1 < 512 ? (r1 & 255) : (r1 - 512);
        int l1 = (r1 >= 512);
        uint4 o;
        o.x = pack2(W[(size_t)s0 * 64 + n_a], W[(size_t)(s0 + 1) * 64 + n_a], l0);
        o.y = pack2(W[(size_t)s1 * 64 + n_a], W[(size_t)(s1 + 1) * 64 + n_a], l1);
        o.z = pack2(W[(size_t)s0 * 64 + n_b], W[(size_t)(s0 + 1) * 64 + n_b], l0);
        o.w = pack2(W[(size_t)s1 * 64 + n_b], W[(size_t)(s1 + 1) * 64 + n_b], l1);
        g_Bo[((size_t)pp * 48 + kc) * 32 + lane] = o;
    }
}

// =====================================================================
// GEMM1 via mma.sync bf16 split (round-15 proven)
// =====================================================================
__global__ void __launch_bounds__(256) gemm1_mma(
        const float* __restrict__ a1, const float* __restrict__ a2) {
    __shared__ float red[4][16][68];
    int tid = threadIdx.x;
    int wm = tid >> 5, lane = tid & 31;
    int p  = wm >> 1, kg = wm & 1;
    int g = lane >> 2, tq = lane & 3;
    int bx = blockIdx.x, by = blockIdx.y;
    int gsel = by >> 2, h = by & 3;
    int mb = bx * 4 + p;

    const uint4* Ab  = &g_A2[(size_t)mb * 48 * 32 + lane];
    const uint4* Bb0 = &g_B2[((size_t)(by * 4 + 0) * 48) * 32 + lane];
    const uint4* Bb1 = &g_B2[((size_t)(by * 4 + 1) * 48) * 32 + lane];
    const uint4* Bb2 = &g_B2[((size_t)(by * 4 + 2) * 48) * 32 + lane];
    const uint4* Bb3 = &g_B2[((size_t)(by * 4 + 3) * 48) * 32 + lane];

    int kc0 = kg * 24;
    float acc[8][4] = {};
    uint4 As_[2], B0_[2], B1_[2], B2_[2], B3_[2];
    As_[0] = Ab [kc0 * 32];
    B0_[0] = Bb0[kc0 * 32];
    B1_[0] = Bb1[kc0 * 32];
    B2_[0] = Bb2[kc0 * 32];
    B3_[0] = Bb3[kc0 * 32];
    #pragma unroll
    for (int t = 0; t < 24; t++) {
        int cur = t & 1, nxt = cur ^ 1;
        if (t < 23) {
            int kc = kc0 + t + 1;
            As_[nxt] = Ab [kc * 32];
            B0_[nxt] = Bb0[kc * 32];
            B1_[nxt] = Bb1[kc * 32];
            B2_[nxt] = Bb2[kc * 32];
            B3_[nxt] = Bb3[kc * 32];
        }
        uint4 A  = As_[cur];
        uint4 B0 = B0_[cur], B1 = B1_[cur], B2 = B2_[cur], B3 = B3_[cur];
        mma_bf16(acc[0], A.x, A.y, A.z, A.w, B0.x, B0.y);
        mma_bf16(acc[1], A.x, A.y, A.z, A.w, B0.z, B0.w);
        mma_bf16(acc[2], A.x, A.y, A.z, A.w, B1.x, B1.y);
        mma_bf16(acc[3], A.x, A.y, A.z, A.w, B1.z, B1.w);
        mma_bf16(acc[4], A.x, A.y, A.z, A.w, B2.x, B2.y);
        mma_bf16(acc[5], A.x, A.y, A.z, A.w, B2.z, B2.w);
        mma_bf16(acc[6], A.x, A.y, A.z, A.w, B3.x, B3.y);
        mma_bf16(acc[7], A.x, A.y, A.z, A.w, B3.z, B3.w);
    }

    if (kg == 1) {
        #pragma unroll
        for (int jt = 0; jt < 8; jt++) {
            int c = jt * 8 + 2 * tq;
            *(float2*)&red[p][g][c]     = make_float2(acc[jt][0], acc[jt][1]);
            *(float2*)&red[p][g + 8][c] = make_float2(acc[jt][2], acc[jt][3]);
        }
    }
    __syncthreads();
    if (kg != 0) return;

    #pragma unroll
    for (int jt = 0; jt < 8; jt++) {
        int c = jt * 8 + 2 * tq;
        float2 v0 = *(const float2*)&red[p][g][c];
        float2 v1 = *(const float2*)&red[p][g + 8][c];
        acc[jt][0] += v0.x; acc[jt][1] += v0.y;
        acc[jt][2] += v1.x; acc[jt][3] += v1.y;
    }

    int gm0 = bx * 64 + p * 16 + g;
    int gm1 = gm0 + 8;
    int n0 = by * 64;
    #pragma unroll
    for (int jt = 0; jt < 8; jt++) {
        int c = n0 + jt * 8 + 2 * tq;
        *(float2*)&g_Wh[gm0][c] = make_float2(acc[jt][0], acc[jt][1]);
        *(float2*)&g_Wh[gm1][c] = make_float2(acc[jt][2], acc[jt][3]);
    }
    const float* av = (gsel ? a2 : a1) + h * 128;
    float s1r0 = 0.f, s2r0 = 0.f, s1r1 = 0.f, s2r1 = 0.f;
    #pragma unroll
    for (int jt = 0; jt < 8; jt++) {
        int c = jt * 8 + 2 * tq;
        float av0 = __ldg(av + c),      av1 = __ldg(av + c + 1);
        float ad0 = __ldg(av + 64 + c), ad1 = __ldg(av + 64 + c + 1);
        s1r0 += acc[jt][0] * av0 + acc[jt][1] * av1;
        s2r0 += acc[jt][0] * ad0 + acc[jt][1] * ad1;
        s1r1 += acc[jt][2] * av0 + acc[jt][3] * av1;
        s2r1 += acc[jt][2] * ad0 + acc[jt][3] * ad1;
    }
    #pragma unroll
    for (int off = 1; off < 4; off <<= 1) {
        s1r0 += __shfl_xor_sync(0xffffffffu, s1r0, off);
        s2r0 += __shfl_xor_sync(0xffffffffu, s2r0, off);
        s1r1 += __shfl_xor_sync(0xffffffffu, s1r1, off);
        s2r1 += __shfl_xor_sync(0xffffffffu, s2r1, off);
    }
    if (tq == 0) {
        g_s1t[gsel][gm0][h] = s1r0;
        g_s2t[gsel][gm0][h] = s2r0;
        g_s1t[gsel][gm1][h] = s1r1;
        g_s2t[gsel][gm1][h] = s2r1;
    }
}

// ---- 4-head gather chunk (attn1) ----
__device__ __forceinline__ void gat_chunk1(const float* __restrict__ tab, int lim,
                                           int cj, float4 ej,
                                           float& ax0, float& ay0, float& ax1, float& ay1,
                                           float& ax2, float& ay2, float& ax3, float& ay3) {
    int kk = 0;
    for (; kk + 2 <= lim; kk += 2) {
        int   ca  = __shfl_sync(0xffffffffu, cj, kk);
        int   cb  = __shfl_sync(0xffffffffu, cj, kk + 1);
        float ea0 = __shfl_sync(0xffffffffu, ej.x, kk);
        float ea1 = __shfl_sync(0xffffffffu, ej.y, kk);
        float ea2 = __shfl_sync(0xffffffffu, ej.z, kk);
        float ea3 = __shfl_sync(0xffffffffu, ej.w, kk);
        float eb0 = __shfl_sync(0xffffffffu, ej.x, kk + 1);
        float eb1 = __shfl_sync(0xffffffffu, ej.y, kk + 1);
        float eb2 = __shfl_sync(0xffffffffu, ej.z, kk + 1);
        float eb3 = __shfl_sync(0xffffffffu, ej.w, kk + 1);
        const float* ra = tab + (size_t)ca * 512;
        const float* rb = tab + (size_t)cb * 512;
        float2 va0 = *(const float2*)(ra);
        float2 va1 = *(const float2*)(ra + 64);
        float2 va2 = *(const float2*)(ra + 128);
        float2 va3 = *(const float2*)(ra + 192);
        float2 vb0 = *(const float2*)(rb);
        float2 vb1 = *(const float2*)(rb + 64);
        float2 vb2 = *(const float2*)(rb + 128);
        float2 vb3 = *(const float2*)(rb + 192);
        ax0 += ea0 * va0.x + eb0 * vb0.x;  ay0 += ea0 * va0.y + eb0 * vb0.y;
        ax1 += ea1 * va1.x + eb1 * vb1.x;  ay1 += ea1 * va1.y + eb1 * vb1.y;
        ax2 += ea2 * va2.x + eb2 * vb2.x;  ay2 += ea2 * va2.y + eb2 * vb2.y;
        ax3 += ea3 * va3.x + eb3 * vb3.x;  ay3 += ea3 * va3.y + eb3 * vb3.y;
    }
    if (kk < lim) {
        int   ca  = __shfl_sync(0xffffffffu, cj, kk);
        float ea0 = __shfl_sync(0xffffffffu, ej.x, kk);
        float ea1 = __shfl_sync(0xffffffffu, ej.y, kk);
        float ea2 = __shfl_sync(0xffffffffu, ej.z, kk);
        float ea3 = __shfl_sync(0xffffffffu, ej.w, kk);
        const float* ra = tab + (size_t)ca * 512;
        float2 va0 = *(const float2*)(ra);
        float2 va1 = *(const float2*)(ra + 64);
        float2 va2 = *(const float2*)(ra + 128);
        float2 va3 = *(const float2*)(ra + 192);
        ax0 += ea0 * va0.x;  ay0 += ea0 * va0.y;
        ax1 += ea1 * va1.x;  ay1 += ea1 * va1.y;
        ax2 += ea2 * va2.x;  ay2 += ea2 * va2.y;
        ax3 += ea3 * va3.x;  ay3 += ea3 * va3.y;
    }
}

// =====================================================================
// Layer-1 attention (round-11 proven)
// =====================================================================
__global__ void attn_layer1() {
    int tid  = threadIdx.x;
    int lane = tid & 31;
    int w    = tid >> 5;
    int n    = w >> 1;
    int g    = w & 1;
    int i    = blockIdx.x * 4 + n;

    int d = g_deg[g][i];
    float4 s1 = *(const float4*)&g_s1t[g][i][0];

    int c0 = 0, c1 = 0;
    float4 e0 = make_float4(0.f, 0.f, 0.f, 0.f);
    float4 e1 = make_float4(0.f, 0.f, 0.f, 0.f);
    if (lane < d) {
        c0 = g_cols[g][i][lane];
        float4 s2 = *(const float4*)&g_s2t[g][c0][0];
        e0.x = lkexp(s1.x + s2.x);  e0.y = lkexp(s1.y + s2.y);
        e0.z = lkexp(s1.z + s2.z);  e0.w = lkexp(s1.w + s2.w);
    }
    if (lane + 32 < d) {
        c1 = g_cols[g][i][lane + 32];
        float4 s2 = *(const float4*)&g_s2t[g][c1][0];
        e1.x = lkexp(s1.x + s2.x);  e1.y = lkexp(s1.y + s2.y);
        e1.z = lkexp(s1.z + s2.z);  e1.w = lkexp(s1.w + s2.w);
    }
    float sx = e0.x + e1.x, sy = e0.y + e1.y, sz = e0.z + e1.z, sw = e0.w + e1.w;
    #pragma unroll
    for (int off = 16; off; off >>= 1) {
        sx += __shfl_xor_sync(0xffffffffu, sx, off);
        sy += __shfl_xor_sync(0xffffffffu, sy, off);
        sz += __shfl_xor_sync(0xffffffffu, sz, off);
        sw += __shfl_xor_sync(0xffffffffu, sw, off);
    }
    float ix = 1.f / sx, iy = 1.f / sy, iz = 1.f / sz, iw = 1.f / sw;

    const float* tab = &g_Wh[0][g * 256 + 2 * lane];
    float ax0 = 0.f, ay0 = 0.f, ax1 = 0.f, ay1 = 0.f;
    float ax2 = 0.f, ay2 = 0.f, ax3 = 0.f, ay3 = 0.f;
    int lim0 = d < 32 ? d : 32;
    int lim1 = d - 32; lim1 = lim1 < 0 ? 0 : lim1;
    gat_chunk1(tab, lim0, c0, e0, ax0, ay0, ax1, ay1, ax2, ay2, ax3, ay3);
    gat_chunk1(tab, lim1, c1, e1, ax0, ay0, ax1, ay1, ax2, ay2, ax3, ay3);

    float* orow = &g_hcat[g][i][2 * lane];
    float2 o;
    o.x = elu1(ax0 * ix);  o.y = elu1(ay0 * ix);  *(float2*)(orow)       = o;
    o.x = elu1(ax1 * iy);  o.y = elu1(ay1 * iy);  *(float2*)(orow + 64)  = o;
    o.x = elu1(ax2 * iz);  o.y = elu1(ay2 * iz);  *(float2*)(orow + 128) = o;
    o.x = elu1(ax3 * iw);  o.y = elu1(ay3 * iw);  *(float2*)(orow + 192) = o;
}

// =====================================================================
// GEMM2 via mma.sync bf16 split, inline A conversion from fp32 hcat.
// grid (128, 2), 256 threads = 2 m-pairs x 4 kg (12 k-steps each).
// =====================================================================
__global__ void __launch_bounds__(256) gemm2_mma(
        const float* __restrict__ ao1, const float* __restrict__ ao2) {
    __shared__ float red[2][3][16][68];
    int tid = threadIdx.x;
    int wm = tid >> 5, lane = tid & 31;
    int p  = wm >> 2, kg = wm & 3;
    int gl = lane >> 2, tq = lane & 3;
    int bx = blockIdx.x, g = blockIdx.y;
    int mb = bx * 2 + p;
    const float* A = &g_hcat[g][0][0];
    const uint4* Bb0 = &g_Bo[((size_t)(g * 4 + 0) * 48) * 32 + lane];
    const uint4* Bb1 = &g_Bo[((size_t)(g * 4 + 1) * 48) * 32 + lane];
    const uint4* Bb2 = &g_Bo[((size_t)(g * 4 + 2) * 48) * 32 + lane];
    const uint4* Bb3 = &g_Bo[((size_t)(g * 4 + 3) * 48) * 32 + lane];
    int r0 = mb * 16 + gl, r1 = r0 + 8;
    const float* Ar0 = A + (size_t)r0 * 256;
    const float* Ar1 = A + (size_t)r1 * 256;

    int kc0 = kg * 12;
    float acc[8][4] = {};
    float2 fa[2][4];
    uint4  fb0[2], fb1[2], fb2[2], fb3[2];
    {
        int c0 = kc0 * 16 + 2 * tq, c1 = c0 + 8;
        int k0 = c0 < 256 ? c0 : (c0 < 512 ? c0 - 256 : c0 - 512);
        int k1 = c1 < 256 ? c1 : (c1 < 512 ? c1 - 256 : c1 - 512);
        fa[0][0] = *(const float2*)(Ar0 + k0);
        fa[0][1] = *(const float2*)(Ar1 + k0);
        fa[0][2] = *(const float2*)(Ar0 + k1);
        fa[0][3] = *(const float2*)(Ar1 + k1);
        fb0[0] = Bb0[kc0 * 32];
        fb1[0] = Bb1[kc0 * 32];
        fb2[0] = Bb2[kc0 * 32];
        fb3[0] = Bb3[kc0 * 32];
    }
    #pragma unroll
    for (int t = 0; t < 12; t++) {
        int cur = t & 1, nxt = cur ^ 1;
        int kc = kc0 + t;
        if (t < 11) {
            int kcn = kc + 1;
            int c0 = kcn * 16 + 2 * tq, c1 = c0 + 8;
            int k0 = c0 < 256 ? c0 : (c0 < 512 ? c0 - 256 : c0 - 512);
            int k1 = c1 < 256 ? c1 : (c1 < 512 ? c1 - 256 : c1 - 512);
            fa[nxt][0] = *(const float2*)(Ar0 + k0);
            fa[nxt][1] = *(const float2*)(Ar1 + k0);
            fa[nxt][2] = *(const float2*)(Ar0 + k1);
            fa[nxt][3] = *(const float2*)(Ar1 + k1);
            fb0[nxt] = Bb0[kcn * 32];
            fb1[nxt] = Bb1[kcn * 32];
            fb2[nxt] = Bb2[kcn * 32];
            fb3[nxt] = Bb3[kcn * 32];
        }
        int lo = (kc >= 16 && kc < 32);
        uint32_t a0 = pack2(fa[cur][0].x, fa[cur][0].y, lo);
        uint32_t a1 = pack2(fa[cur][1].x, fa[cur][1].y, lo);
        uint32_t a2 = pack2(fa[cur][2].x, fa[cur][2].y, lo);
        uint32_t a3 = pack2(fa[cur][3].x, fa[cur][3].y, lo);
        uint4 B0 = fb0[cur], B1 = fb1[cur], B2 = fb2[cur], B3 = fb3[cur];
        mma_bf16(acc[0], a0, a1, a2, a3, B0.x, B0.y);
        mma_bf16(acc[1], a0, a1, a2, a3, B0.z, B0.w);
        mma_bf16(acc[2], a0, a1, a2, a3, B1.x, B1.y);
        mma_bf16(acc[3], a0, a1, a2, a3, B1.z, B1.w);
        mma_bf16(acc[4], a0, a1, a2, a3, B2.x, B2.y);
        mma_bf16(acc[5], a0, a1, a2, a3, B2.z, B2.w);
        mma_bf16(acc[6], a0, a1, a2, a3, B3.x, B3.y);
        mma_bf16(acc[7], a0, a1, a2, a3, B3.z, B3.w);
    }

    if (kg != 0) {
        #pragma unroll
        for (int jt = 0; jt < 8; jt++) {
            int c = jt * 8 + 2 * tq;
            *(float2*)&red[p][kg - 1][gl][c]     = make_float2(acc[jt][0], acc[jt][1]);
            *(float2*)&red[p][kg - 1][gl + 8][c] = make_float2(acc[jt][2], acc[jt][3]);
        }
    }
    __syncthreads();
    if (kg != 0) return;

    #pragma unroll
    for (int q = 0; q < 3; q++) {
        #pragma unroll
        for (int jt = 0; jt < 8; jt++) {
            int c = jt * 8 + 2 * tq;
            float2 v0 = *(const float2*)&red[p][q][gl][c];
            float2 v1 = *(const float2*)&red[p][q][gl + 8][c];
            acc[jt][0] += v0.x; acc[jt][1] += v0.y;
            acc[jt][2] += v1.x; acc[jt][3] += v1.y;
        }
    }

    #pragma unroll
    for (int jt = 0; jt < 8; jt++) {
        int c = jt * 8 + 2 * tq;
        *(float2*)&g_Wh2[g][r0][c] = make_float2(acc[jt][0], acc[jt][1]);
        *(float2*)&g_Wh2[g][r1][c] = make_float2(acc[jt][2], acc[jt][3]);
    }
    const float* ao = g ? ao2 : ao1;
    float s1r0 = 0.f, s2r0 = 0.f, s1r1 = 0.f, s2r1 = 0.f;
    #pragma unroll
    for (int jt = 0; jt < 8; jt++) {
        int c = jt * 8 + 2 * tq;
        float av0 = __ldg(ao + c),      av1 = __ldg(ao + c + 1);
        float ad0 = __ldg(ao + 64 + c), ad1 = __ldg(ao + 64 + c + 1);
        s1r0 += acc[jt][0] * av0 + acc[jt][1] * av1;
        s2r0 += acc[jt][0] * ad0 + acc[jt][1] * ad1;
        s1r1 += acc[jt][2] * av0 + acc[jt][3] * av1;
        s2r1 += acc[jt][2] * ad0 + acc[jt][3] * ad1;
    }
    #pragma unroll
    for (int off = 1; off < 4; off <<= 1) {
        s1r0 += __shfl_xor_sync(0xffffffffu, s1r0, off);
        s2r0 += __shfl_xor_sync(0xffffffffu, s2r0, off);
        s1r1 += __shfl_xor_sync(0xffffffffu, s1r1, off);
        s2r1 += __shfl_xor_sync(0xffffffffu, s2r1, off);
    }
    if (tq == 0) {
        g_s1o[g][r0] = s1r0;
        g_s2o[g][r0] = s2r0;
        g_s1o[g][r1] = s1r1;
        g_s2o[g][r1] = s2r1;
    }
}

// ---- scalar gather chunk (attn2) ----
__device__ __forceinline__ void gat_chunk2(const float* __restrict__ tab, int lim,
                                           int cj, float ej, float& ax, float& ay) {
    int kk = 0;
    for (; kk + 4 <= lim; kk += 4) {
        int   c0 = __shfl_sync(0xffffffffu, cj, kk);
        int   c1 = __shfl_sync(0xffffffffu, cj, kk + 1);
        int   c2 = __shfl_sync(0xffffffffu, cj, kk + 2);
        int   c3 = __shfl_sync(0xffffffffu, cj, kk + 3);
        float e0 = __shfl_sync(0xffffffffu, ej, kk);
        float e1 = __shfl_sync(0xffffffffu, ej, kk + 1);
        float e2 = __shfl_sync(0xffffffffu, ej, kk + 2);
        float e3 = __shfl_sync(0xffffffffu, ej, kk + 3);
        float2 v0 = *(const float2*)(tab + (size_t)c0 * 64);
        float2 v1 = *(const float2*)(tab + (size_t)c1 * 64);
        float2 v2 = *(const float2*)(tab + (size_t)c2 * 64);
        float2 v3 = *(const float2*)(tab + (size_t)c3 * 64);
        ax += e0 * v0.x + e1 * v1.x + e2 * v2.x + e3 * v3.x;
        ay += e0 * v0.y + e1 * v1.y + e2 * v2.y + e3 * v3.y;
    }
    for (; kk < lim; kk++) {
        int   c = __shfl_sync(0xffffffffu, cj, kk);
        float e = __shfl_sync(0xffffffffu, ej, kk);
        float2 v = *(const float2*)(tab + (size_t)c * 64);
        ax += e * v.x;
        ay += e * v.y;
    }
}

// =====================================================================
// Layer-2 attention + ELU + semantic fusion (round-11 proven)
// =====================================================================
__global__ void attn2_final(const float* __restrict__ Wp1, const float* __restrict__ bp1,
                            const float* __restrict__ Wp2, float* __restrict__ out) {
    int tid  = threadIdx.x;
    int lane = tid & 31;
    int w    = tid >> 5;
    int n    = w >> 1;
    int g    = w & 1;
    int i    = blockIdx.x * 4 + n;

    __shared__ float se[4][2][64];
    __shared__ float sw[4][2];

    int d = g_deg[g][i];
    float s1v = g_s1o[g][i];
    int c0 = 0, c1 = 0;
    float e0 = 0.f, e1 = 0.f;
    if (lane < d) {
        c0 = g_cols[g][i][lane];
        e0 = lkexp(s1v + g_s2o[g][c0]);
    }
    if (lane + 32 < d) {
        c1 = g_cols[g][i][lane + 32];
        e1 = lkexp(s1v + g_s2o[g][c1]);
    }
    float sum = e0 + e1;
    #pragma unroll
    for (int off = 16; off; off >>= 1) sum += __shfl_xor_sync(0xffffffffu, sum, off);
    float inv = 1.f / sum;

    const float* tab = &g_Wh2[g][0][2 * lane];
    float ax = 0.f, ay = 0.f;
    int lim0 = d < 32 ? d : 32;
    int lim1 = d - 32; lim1 = lim1 < 0 ? 0 : lim1;
    gat_chunk2(tab, lim0, c0, e0, ax, ay);
    gat_chunk2(tab, lim1, c1, e1, ax, ay);

    ax *= inv; ay *= inv;
    se[n][g][2 * lane]     = elu1(ax);
    se[n][g][2 * lane + 1] = elu1(ay);
    __syncthreads();

    if (tid < 128) {
        int pn = tid >> 5, pg = (tid >> 4) & 1, p = tid & 15;
        float s = __ldg(bp1 + p);
        #pragma unroll
        for (int f = 0; f < 64; f++) s += se[pn][pg][f] * __ldg(Wp1 + f * NPROJ + p);
        float e2x = __expf(2.f * s);
        float t = __fdividef(e2x - 1.f, e2x + 1.f);
        float wv = t * __ldg(Wp2 + p);
        wv += __shfl_xor_sync(0xffffffffu, wv, 1);
        wv += __shfl_xor_sync(0xffffffffu, wv, 2);
        wv += __shfl_xor_sync(0xffffffffu, wv, 4);
        wv += __shfl_xor_sync(0xffffffffu, wv, 8);
        if (p == 0) sw[pn][pg] = wv;
    }
    __syncthreads();

    int on = tid >> 6, f = tid & 63;
    float w0 = sw[on][0], w1 = sw[on][1];
    float mm = fmaxf(w0, w1);
    float b0 = __expf(w0 - mm), b1 = __expf(w1 - mm);
    float ib = 1.f / (b0 + b1);
    int oi = blockIdx.x * 4 + on;
    out[(size_t)oi * 64 + f] = (b0 * se[on][0][f] + b1 * se[on][1][f]) * ib;
}

// ---------------- launch ----------------
extern "C" void kernel_launch(void* const* d_in, const int* in_sizes, int n_in,
                              void* d_out, int out_size) {
    const float* x    = (const float*)d_in[0];
    const float* sadj = (const float*)d_in[1];
    const float* sadj2= (const float*)d_in[2];
    const float* W1   = (const float*)d_in[3];
    const float* a1   = (const float*)d_in[4];
    const float* Wo1  = (const float*)d_in[5];
    const float* ao1  = (const float*)d_in[6];
    const float* W2   = (const float*)d_in[7];
    const float* a2   = (const float*)d_in[8];
    const float* Wo2  = (const float*)d_in[9];
    const float* ao2  = (const float*)d_in[10];
    const float* Wp1  = (const float*)d_in[11];
    const float* bp1  = (const float*)d_in[12];
    const float* Wp2  = (const float*)d_in[13];
    float* out = (float*)d_out;

    static cudaStream_t s_side = nullptr;
    static cudaEvent_t  ev_fork = nullptr, ev_join = nullptr;
    if (!s_side) {
        cudaStreamCreateWithFlags(&s_side, cudaStreamNonBlocking);
        cudaEventCreateWithFlags(&ev_fork, cudaEventDisableTiming);
        cudaEventCreateWithFlags(&ev_join, cudaEventDisableTiming);
    }

    cudaEventRecord(ev_fork, 0);
    cudaStreamWaitEvent(s_side, ev_fork, 0);
    csr_build<<<1024, 256, 0, s_side>>>(sadj, sadj2);
    cudaEventRecord(ev_join, s_side);

    prep_all<<<1776, 256>>>(x, W1, W2, Wo1, Wo2);
    gemm1_mma<<<dim3(64, 8), 256>>>(a1, a2);

    cudaStreamWaitEvent(0, ev_join, 0);

    attn_layer1<<<1024, 256>>>();
    gemm2_mma<<<dim3(128, 2), 256>>>(ao1, ao2);
    attn2_final<<<1024, 256>>>(Wp1, bp1, Wp2, out);
}

// round 17
// speedup vs baseline: 1.4425x; 1.0532x over previous
#include <cuda_runtime.h>
#include <cuda_bf16.h>
#include <math.h>
#include <stdint.h>

#define N_NODES 4096
#define FIN     256
#define NHEAD   4
#define FHID    64
#define FFIN    64
#define NPROJ   16
#define MAXD    128

// ---------------- scratch ----------------
__device__ int   g_cols[2][N_NODES][MAXD];
__device__ int   g_deg [2][N_NODES];
__device__ float g_Wh  [N_NODES][512];
__device__ float g_s1t [2][N_NODES][4];
__device__ float g_s2t [2][N_NODES][4];
__device__ float g_hcat[2][N_NODES][256];
__device__ float g_Wh2 [2][N_NODES][64];
__device__ float g_s1o [2][N_NODES];
__device__ float g_s2o [2][N_NODES];
__device__ uint4 g_A2[256 * 48 * 32];
__device__ uint4 g_B2[32 * 48 * 32];
__device__ uint4 g_Bo[8 * 48 * 32];

__device__ __forceinline__ float lkexp(float z) {
    z = z >= 0.f ? z : 0.2f * z;
    return __expf(z);
}
__device__ __forceinline__ float elu1(float v) {
    return v > 0.f ? v : (__expf(v) - 1.f);
}

__device__ __forceinline__ uint32_t pack2(float v0, float v1, int lo_part) {
    __nv_bfloat16 h0 = __float2bfloat16(v0);
    __nv_bfloat16 h1 = __float2bfloat16(v1);
    if (lo_part) {
        h0 = __float2bfloat16(v0 - __bfloat162float(h0));
        h1 = __float2bfloat16(v1 - __bfloat162float(h1));
    }
    uint32_t u0, u1;
    u0 = (uint32_t)*(uint16_t*)&h0;
    u1 = (uint32_t)*(uint16_t*)&h1;
    return u0 | (u1 << 16);
}

__device__ __forceinline__ void mma_bf16(float* d,
        uint32_t a0, uint32_t a1, uint32_t a2, uint32_t a3,
        uint32_t b0, uint32_t b1) {
    asm volatile(
        "mma.sync.aligned.m16n8k16.row.col.f32.bf16.bf16.f32 "
        "{%0,%1,%2,%3}, {%4,%5,%6,%7}, {%8,%9}, {%0,%1,%2,%3};"
        : "+f"(d[0]), "+f"(d[1]), "+f"(d[2]), "+f"(d[3])
        : "r"(a0), "r"(a1), "r"(a2), "r"(a3), "r"(b0), "r"(b1));
}

// =====================================================================
// CSR build (round-11 proven)
// =====================================================================
__device__ __forceinline__ void place_bits(unsigned nb, int cb, int& pos, int* __restrict__ row) {
    while (nb) {
        int b = __ffs(nb) - 1;
        nb &= nb - 1;
        if (pos < MAXD) row[pos] = cb + b;
        pos++;
    }
}

__global__ void csr_build(const float* __restrict__ m0, const float* __restrict__ m1) {
    int tid  = threadIdx.x;
    int w    = blockIdx.x * 8 + (tid >> 5);
    int lane = tid & 31;
    int g = w >> 12, r = w & 4095;
    const float4* mask = (const float4*)((g ? m1 : m0) + (size_t)r * N_NODES);
    int* row = &g_cols[g][r][0];
    int cnt = 0;
    for (int jb = 0; jb < 1024; jb += 128) {
        float4 v0 = mask[jb + lane];
        float4 v1 = mask[jb + 32 + lane];
        float4 v2 = mask[jb + 64 + lane];
        float4 v3 = mask[jb + 96 + lane];
        unsigned n0 = (v0.x > 0.f) | ((v0.y > 0.f) << 1) | ((v0.z > 0.f) << 2) | ((v0.w > 0.f) << 3);
        unsigned n1 = (v1.x > 0.f) | ((v1.y > 0.f) << 1) | ((v1.z > 0.f) << 2) | ((v1.w > 0.f) << 3);
        unsigned n2 = (v2.x > 0.f) | ((v2.y > 0.f) << 1) | ((v2.z > 0.f) << 2) | ((v2.w > 0.f) << 3);
        unsigned n3 = (v3.x > 0.f) | ((v3.y > 0.f) << 1) | ((v3.z > 0.f) << 2) | ((v3.w > 0.f) << 3);
        int c = __popc(n0) + __popc(n1) + __popc(n2) + __popc(n3);
        int s = c;
        #pragma unroll
        for (int off = 1; off < 32; off <<= 1) {
            int t = __shfl_up_sync(0xffffffffu, s, off);
            if (lane >= off) s += t;
        }
        int pos = cnt + s - c;
        cnt += __shfl_sync(0xffffffffu, s, 31);
        if (c) {
            place_bits(n0, (jb + lane) * 4,      pos, row);
            place_bits(n1, (jb + 32 + lane) * 4, pos, row);
            place_bits(n2, (jb + 64 + lane) * 4, pos, row);
            place_bits(n3, (jb + 96 + lane) * 4, pos, row);
        }
    }
    if (lane == 0) g_deg[g][r] = cnt < MAXD ? cnt : MAXD;
}

// =====================================================================
// prep_all: merged operand packing (round-16 proven)
// =====================================================================
__global__ void prep_all(const float* __restrict__ x,
                         const float* __restrict__ W1, const float* __restrict__ W2,
                         const float* __restrict__ Wo1, const float* __restrict__ Wo2) {
    int bid = blockIdx.x;
    if (bid < 1536) {
        int idx = bid * 256 + threadIdx.x;
        int lane = idx & 31;
        int kc   = (idx >> 5) % 48;
        int mb   = idx / (48 * 32);
        int gl = lane >> 2, tq = lane & 3;
        int row0 = mb * 16 + gl, row1 = row0 + 8;
        int c0 = kc * 16 + 2 * tq;
        int c1 = c0 + 8;
        int s0 = c0 < 256 ? c0 : (c0 < 512 ? c0 - 256 : c0 - 512);
        int l0 = (c0 >= 256 && c0 < 512);
        int s1 = c1 < 256 ? c1 : (c1 < 512 ? c1 - 256 : c1 - 512);
        int l1 = (c1 >= 256 && c1 < 512);
        float2 v00 = *(const float2*)(x + (size_t)row0 * FIN + s0);
        float2 v10 = *(const float2*)(x + (size_t)row1 * FIN + s0);
        float2 v01 = *(const float2*)(x + (size_t)row0 * FIN + s1);
        float2 v11 = *(const float2*)(x + (size_t)row1 * FIN + s1);
        uint4 o;
        o.x = pack2(v00.x, v00.y, l0);
        o.y = pack2(v10.x, v10.y, l0);
        o.z = pack2(v01.x, v01.y, l1);
        o.w = pack2(v11.x, v11.y, l1);
        g_A2[((size_t)mb * 48 + kc) * 32 + lane] = o;
    } else if (bid < 1728) {
        int idx = (bid - 1536) * 256 + threadIdx.x;
        int lane = idx & 31;
        int kc   = (idx >> 5) % 48;
        int pp   = idx / (48 * 32);
        int by = pp >> 2, p = pp & 3;
        int gsel = by >> 2, h = by & 3;
        const float* W = (gsel ? W2 : W1) + (size_t)h * FIN * FHID;
        int gl = lane >> 2, tq = lane & 3;
        int n_a = 16 * p + gl, n_b = n_a + 8;
        int r0 = kc * 16 + 2 * tq;
        int r1 = r0 + 8;
        int s0 = r0 < 512 ? (r0 & 255) : (r0 - 512);
        int l0 = (r0 >= 512);
        int s1 = r1 < 512 ? (r1 & 255) : (r1 - 512);
        int l1 = (r1 >= 512);
        uint4 o;
        o.x = pack2(W[(size_t)s0 * 64 + n_a], W[(size_t)(s0 + 1) * 64 + n_a], l0);
        o.y = pack2(W[(size_t)s1 * 64 + n_a], W[(size_t)(s1 + 1) * 64 + n_a], l1);
        o.z = pack2(W[(size_t)s0 * 64 + n_b], W[(size_t)(s0 + 1) * 64 + n_b], l0);
        o.w = pack2(W[(size_t)s1 * 64 + n_b], W[(size_t)(s1 + 1) * 64 + n_b], l1);
        g_B2[((size_t)pp * 48 + kc) * 32 + lane] = o;
    } else {
        int idx = (bid - 1728) * 256 + threadIdx.x;
        int lane = idx & 31;
        int kc   = (idx >> 5) % 48;
        int pp   = idx / (48 * 32);
        int g2 = pp >> 2, p = pp & 3;
        const float* W = g2 ? Wo2 : Wo1;
        int gl = lane >> 2, tq = lane & 3;
        int n_a = 16 * p + gl, n_b = n_a + 8;
        int r0 = kc * 16 + 2 * tq;
        int r1 = r0 + 8;
        int s0 = r0 < 512 ? (r0 & 255) : (r0 - 512);
        int l0 = (r0 >= 512);
        int s1 = r1 < 512 ? (r1 & 255) : (r1 - 512);
        int l1 = (r1 >= 512);
        uint4 o;
        o.x = pack2(W[(size_t)s0 * 64 + n_a], W[(size_t)(s0 + 1) * 64 + n_a], l0);
        o.y = pack2(W[(size_t)s1 * 64 + n_a], W[(size_t)(s1 + 1) * 64 + n_a], l1);
        o.z = pack2(W[(size_t)s0 * 64 + n_b], W[(size_t)(s0 + 1) * 64 + n_b], l0);
        o.w = pack2(W[(size_t)s1 * 64 + n_b], W[(size_t)(s1 + 1) * 64 + n_b], l1);
        g_Bo[((size_t)pp * 48 + kc) * 32 + lane] = o;
    }
}

// =====================================================================
// GEMM1 via mma.sync bf16 split (round-15 proven)
// =====================================================================
__global__ void __launch_bounds__(256) gemm1_mma(
        const float* __restrict__ a1, const float* __restrict__ a2) {
    __shared__ float red[4][16][68];
    int tid = threadIdx.x;
    int wm = tid >> 5, lane = tid & 31;
    int p  = wm >> 1, kg = wm & 1;
    int g = lane >> 2, tq = lane & 3;
    int bx = blockIdx.x, by = blockIdx.y;
    int gsel = by >> 2, h = by & 3;
    int mb = bx * 4 + p;

    const uint4* Ab  = &g_A2[(size_t)mb * 48 * 32 + lane];
    const uint4* Bb0 = &g_B2[((size_t)(by * 4 + 0) * 48) * 32 + lane];
    const uint4* Bb1 = &g_B2[((size_t)(by * 4 + 1) * 48) * 32 + lane];
    const uint4* Bb2 = &g_B2[((size_t)(by * 4 + 2) * 48) * 32 + lane];
    const uint4* Bb3 = &g_B2[((size_t)(by * 4 + 3) * 48) * 32 + lane];

    int kc0 = kg * 24;
    float acc[8][4] = {};
    uint4 As_[2], B0_[2], B1_[2], B2_[2], B3_[2];
    As_[0] = Ab [kc0 * 32];
    B0_[0] = Bb0[kc0 * 32];
    B1_[0] = Bb1[kc0 * 32];
    B2_[0] = Bb2[kc0 * 32];
    B3_[0] = Bb3[kc0 * 32];
    #pragma unroll
    for (int t = 0; t < 24; t++) {
        int cur = t & 1, nxt = cur ^ 1;
        if (t < 23) {
            int kc = kc0 + t + 1;
            As_[nxt] = Ab [kc * 32];
            B0_[nxt] = Bb0[kc * 32];
            B1_[nxt] = Bb1[kc * 32];
            B2_[nxt] = Bb2[kc * 32];
            B3_[nxt] = Bb3[kc * 32];
        }
        uint4 A  = As_[cur];
        uint4 B0 = B0_[cur], B1 = B1_[cur], B2 = B2_[cur], B3 = B3_[cur];
        mma_bf16(acc[0], A.x, A.y, A.z, A.w, B0.x, B0.y);
        mma_bf16(acc[1], A.x, A.y, A.z, A.w, B0.z, B0.w);
        mma_bf16(acc[2], A.x, A.y, A.z, A.w, B1.x, B1.y);
        mma_bf16(acc[3], A.x, A.y, A.z, A.w, B1.z, B1.w);
        mma_bf16(acc[4], A.x, A.y, A.z, A.w, B2.x, B2.y);
        mma_bf16(acc[5], A.x, A.y, A.z, A.w, B2.z, B2.w);
        mma_bf16(acc[6], A.x, A.y, A.z, A.w, B3.x, B3.y);
        mma_bf16(acc[7], A.x, A.y, A.z, A.w, B3.z, B3.w);
    }

    if (kg == 1) {
        #pragma unroll
        for (int jt = 0; jt < 8; jt++) {
            int c = jt * 8 + 2 * tq;
            *(float2*)&red[p][g][c]     = make_float2(acc[jt][0], acc[jt][1]);
            *(float2*)&red[p][g + 8][c] = make_float2(acc[jt][2], acc[jt][3]);
        }
    }
    __syncthreads();
    if (kg != 0) return;

    #pragma unroll
    for (int jt = 0; jt < 8; jt++) {
        int c = jt * 8 + 2 * tq;
        float2 v0 = *(const float2*)&red[p][g][c];
        float2 v1 = *(const float2*)&red[p][g + 8][c];
        acc[jt][0] += v0.x; acc[jt][1] += v0.y;
        acc[jt][2] += v1.x; acc[jt][3] += v1.y;
    }

    int gm0 = bx * 64 + p * 16 + g;
    int gm1 = gm0 + 8;
    int n0 = by * 64;
    #pragma unroll
    for (int jt = 0; jt < 8; jt++) {
        int c = n0 + jt * 8 + 2 * tq;
        *(float2*)&g_Wh[gm0][c] = make_float2(acc[jt][0], acc[jt][1]);
        *(float2*)&g_Wh[gm1][c] = make_float2(acc[jt][2], acc[jt][3]);
    }
    const float* av = (gsel ? a2 : a1) + h * 128;
    float s1r0 = 0.f, s2r0 = 0.f, s1r1 = 0.f, s2r1 = 0.f;
    #pragma unroll
    for (int jt = 0; jt < 8; jt++) {
        int c = jt * 8 + 2 * tq;
        float av0 = __ldg(av + c),      av1 = __ldg(av + c + 1);
        float ad0 = __ldg(av + 64 + c), ad1 = __ldg(av + 64 + c + 1);
        s1r0 += acc[jt][0] * av0 + acc[jt][1] * av1;
        s2r0 += acc[jt][0] * ad0 + acc[jt][1] * ad1;
        s1r1 += acc[jt][2] * av0 + acc[jt][3] * av1;
        s2r1 += acc[jt][2] * ad0 + acc[jt][3] * ad1;
    }
    #pragma unroll
    for (int off = 1; off < 4; off <<= 1) {
        s1r0 += __shfl_xor_sync(0xffffffffu, s1r0, off);
        s2r0 += __shfl_xor_sync(0xffffffffu, s2r0, off);
        s1r1 += __shfl_xor_sync(0xffffffffu, s1r1, off);
        s2r1 += __shfl_xor_sync(0xffffffffu, s2r1, off);
    }
    if (tq == 0) {
        g_s1t[gsel][gm0][h] = s1r0;
        g_s2t[gsel][gm0][h] = s2r0;
        g_s1t[gsel][gm1][h] = s1r1;
        g_s2t[gsel][gm1][h] = s2r1;
    }
}

// =====================================================================
// Layer-1 attention: one warp per (node, graph, head-pair).
// grid 2048 x 256 = 16384 warps. Lane owns 4 feats (one LDG.128/edge).
// =====================================================================
__global__ void attn_layer1() {
    int tid  = threadIdx.x;
    int lane = tid & 31;
    int w    = tid >> 5;             // 0..7 = 2 nodes x 2 g x 2 hp
    int i    = blockIdx.x * 2 + (w >> 2);
    int g    = (w >> 1) & 1;
    int hp   = w & 1;

    int d = g_deg[g][i];
    float2 s1 = *(const float2*)&g_s1t[g][i][hp * 2];

    int c0 = 0, c1 = 0;
    float2 e0 = make_float2(0.f, 0.f), e1 = make_float2(0.f, 0.f);
    if (lane < d) {
        c0 = g_cols[g][i][lane];
        float2 s2 = *(const float2*)&g_s2t[g][c0][hp * 2];
        e0.x = lkexp(s1.x + s2.x);
        e0.y = lkexp(s1.y + s2.y);
    }
    if (lane + 32 < d) {
        c1 = g_cols[g][i][lane + 32];
        float2 s2 = *(const float2*)&g_s2t[g][c1][hp * 2];
        e1.x = lkexp(s1.x + s2.x);
        e1.y = lkexp(s1.y + s2.y);
    }
    float sx = e0.x + e1.x, sy = e0.y + e1.y;
    #pragma unroll
    for (int off = 16; off; off >>= 1) {
        sx += __shfl_xor_sync(0xffffffffu, sx, off);
        sy += __shfl_xor_sync(0xffffffffu, sy, off);
    }
    bool loh = (lane < 16);
    float inv = loh ? (1.f / sx) : (1.f / sy);

    // gather: lane owns feats [hp*128 + 4*lane, +4); head = hp*2 + (lane>=16)
    const float* tab = &g_Wh[0][g * 256 + hp * 128 + 4 * lane];
    float ac0 = 0.f, ac1 = 0.f, ac2 = 0.f, ac3 = 0.f;

    // chunk 0 (edges 0..min(d,32))
    {
        int lim = d < 32 ? d : 32;
        int kk = 0;
        for (; kk + 2 <= lim; kk += 2) {
            int   ca = __shfl_sync(0xffffffffu, c0, kk);
            int   cb = __shfl_sync(0xffffffffu, c0, kk + 1);
            float eax = __shfl_sync(0xffffffffu, e0.x, kk);
            float eay = __shfl_sync(0xffffffffu, e0.y, kk);
            float ebx = __shfl_sync(0xffffffffu, e0.x, kk + 1);
            float eby = __shfl_sync(0xffffffffu, e0.y, kk + 1);
            float ea = loh ? eax : eay;
            float eb = loh ? ebx : eby;
            float4 va = *(const float4*)(tab + (size_t)ca * 512);
            float4 vb = *(const float4*)(tab + (size_t)cb * 512);
            ac0 += ea * va.x + eb * vb.x;
            ac1 += ea * va.y + eb * vb.y;
            ac2 += ea * va.z + eb * vb.z;
            ac3 += ea * va.w + eb * vb.w;
        }
        if (kk < lim) {
            int   ca = __shfl_sync(0xffffffffu, c0, kk);
            float eax = __shfl_sync(0xffffffffu, e0.x, kk);
            float eay = __shfl_sync(0xffffffffu, e0.y, kk);
            float ea = loh ? eax : eay;
            float4 va = *(const float4*)(tab + (size_t)ca * 512);
            ac0 += ea * va.x; ac1 += ea * va.y; ac2 += ea * va.z; ac3 += ea * va.w;
        }
    }
    // chunk 1 (edges 32..d)
    {
        int lim = d - 32; lim = lim < 0 ? 0 : lim;
        int kk = 0;
        for (; kk + 2 <= lim; kk += 2) {
            int   ca = __shfl_sync(0xffffffffu, c1, kk);
            int   cb = __shfl_sync(0xffffffffu, c1, kk + 1);
            float eax = __shfl_sync(0xffffffffu, e1.x, kk);
            float eay = __shfl_sync(0xffffffffu, e1.y, kk);
            float ebx = __shfl_sync(0xffffffffu, e1.x, kk + 1);
            float eby = __shfl_sync(0xffffffffu, e1.y, kk + 1);
            float ea = loh ? eax : eay;
            float eb = loh ? ebx : eby;
            float4 va = *(const float4*)(tab + (size_t)ca * 512);
            float4 vb = *(const float4*)(tab + (size_t)cb * 512);
            ac0 += ea * va.x + eb * vb.x;
            ac1 += ea * va.y + eb * vb.y;
            ac2 += ea * va.z + eb * vb.z;
            ac3 += ea * va.w + eb * vb.w;
        }
        if (kk < lim) {
            int   ca = __shfl_sync(0xffffffffu, c1, kk);
            float eax = __shfl_sync(0xffffffffu, e1.x, kk);
            float eay = __shfl_sync(0xffffffffu, e1.y, kk);
            float ea = loh ? eax : eay;
            float4 va = *(const float4*)(tab + (size_t)ca * 512);
            ac0 += ea * va.x; ac1 += ea * va.y; ac2 += ea * va.z; ac3 += ea * va.w;
        }
    }

    float4 o;
    o.x = elu1(ac0 * inv);
    o.y = elu1(ac1 * inv);
    o.z = elu1(ac2 * inv);
    o.w = elu1(ac3 * inv);
    *(float4*)&g_hcat[g][i][hp * 128 + 4 * lane] = o;
}

// =====================================================================
// GEMM2 via mma.sync bf16 split (round-16 proven)
// =====================================================================
__global__ void __launch_bounds__(256) gemm2_mma(
        const float* __restrict__ ao1, const float* __restrict__ ao2) {
    __shared__ float red[2][3][16][68];
    int tid = threadIdx.x;
    int wm = tid >> 5, lane = tid & 31;
    int p  = wm >> 2, kg = wm & 3;
    int gl = lane >> 2, tq = lane & 3;
    int bx = blockIdx.x, g = blockIdx.y;
    int mb = bx * 2 + p;
    const float* A = &g_hcat[g][0][0];
    const uint4* Bb0 = &g_Bo[((size_t)(g * 4 + 0) * 48) * 32 + lane];
    const uint4* Bb1 = &g_Bo[((size_t)(g * 4 + 1) * 48) * 32 + lane];
    const uint4* Bb2 = &g_Bo[((size_t)(g * 4 + 2) * 48) * 32 + lane];
    const uint4* Bb3 = &g_Bo[((size_t)(g * 4 + 3) * 48) * 32 + lane];
    int r0 = mb * 16 + gl, r1 = r0 + 8;
    const float* Ar0 = A + (size_t)r0 * 256;
    const float* Ar1 = A + (size_t)r1 * 256;

    int kc0 = kg * 12;
    float acc[8][4] = {};
    float2 fa[2][4];
    uint4  fb0[2], fb1[2], fb2[2], fb3[2];
    {
        int c0 = kc0 * 16 + 2 * tq, c1 = c0 + 8;
        int k0 = c0 < 256 ? c0 : (c0 < 512 ? c0 - 256 : c0 - 512);
        int k1 = c1 < 256 ? c1 : (c1 < 512 ? c1 - 256 : c1 - 512);
        fa[0][0] = *(const float2*)(Ar0 + k0);
        fa[0][1] = *(const float2*)(Ar1 + k0);
        fa[0][2] = *(const float2*)(Ar0 + k1);
        fa[0][3] = *(const float2*)(Ar1 + k1);
        fb0[0] = Bb0[kc0 * 32];
        fb1[0] = Bb1[kc0 * 32];
        fb2[0] = Bb2[kc0 * 32];
        fb3[0] = Bb3[kc0 * 32];
    }
    #pragma unroll
    for (int t = 0; t < 12; t++) {
        int cur = t & 1, nxt = cur ^ 1;
        int kc = kc0 + t;
        if (t < 11) {
            int kcn = kc + 1;
            int c0 = kcn * 16 + 2 * tq, c1 = c0 + 8;
            int k0 = c0 < 256 ? c0 : (c0 < 512 ? c0 - 256 : c0 - 512);
            int k1 = c1 < 256 ? c1 : (c1 < 512 ? c1 - 256 : c1 - 512);
            fa[nxt][0] = *(const float2*)(Ar0 + k0);
            fa[nxt][1] = *(const float2*)(Ar1 + k0);
            fa[nxt][2] = *(const float2*)(Ar0 + k1);
            fa[nxt][3] = *(const float2*)(Ar1 + k1);
            fb0[nxt] = Bb0[kcn * 32];
            fb1[nxt] = Bb1[kcn * 32];
            fb2[nxt] = Bb2[kcn * 32];
            fb3[nxt] = Bb3[kcn * 32];
        }
        int lo = (kc >= 16 && kc < 32);
        uint32_t a0 = pack2(fa[cur][0].x, fa[cur][0].y, lo);
        uint32_t a1 = pack2(fa[cur][1].x, fa[cur][1].y, lo);
        uint32_t a2 = pack2(fa[cur][2].x, fa[cur][2].y, lo);
        uint32_t a3 = pack2(fa[cur][3].x, fa[cur][3].y, lo);
        uint4 B0 = fb0[cur], B1 = fb1[cur], B2 = fb2[cur], B3 = fb3[cur];
        mma_bf16(acc[0], a0, a1, a2, a3, B0.x, B0.y);
        mma_bf16(acc[1], a0, a1, a2, a3, B0.z, B0.w);
        mma_bf16(acc[2], a0, a1, a2, a3, B1.x, B1.y);
        mma_bf16(acc[3], a0, a1, a2, a3, B1.z, B1.w);
        mma_bf16(acc[4], a0, a1, a2, a3, B2.x, B2.y);
        mma_bf16(acc[5], a0, a1, a2, a3, B2.z, B2.w);
        mma_bf16(acc[6], a0, a1, a2, a3, B3.x, B3.y);
        mma_bf16(acc[7], a0, a1, a2, a3, B3.z, B3.w);
    }

    if (kg != 0) {
        #pragma unroll
        for (int jt = 0; jt < 8; jt++) {
            int c = jt * 8 + 2 * tq;
            *(float2*)&red[p][kg - 1][gl][c]     = make_float2(acc[jt][0], acc[jt][1]);
            *(float2*)&red[p][kg - 1][gl + 8][c] = make_float2(acc[jt][2], acc[jt][3]);
        }
    }
    __syncthreads();
    if (kg != 0) return;

    #pragma unroll
    for (int q = 0; q < 3; q++) {
        #pragma unroll
        for (int jt = 0; jt < 8; jt++) {
            int c = jt * 8 + 2 * tq;
            float2 v0 = *(const float2*)&red[p][q][gl][c];
            float2 v1 = *(const float2*)&red[p][q][gl + 8][c];
            acc[jt][0] += v0.x; acc[jt][1] += v0.y;
            acc[jt][2] += v1.x; acc[jt][3] += v1.y;
        }
    }

    #pragma unroll
    for (int jt = 0; jt < 8; jt++) {
        int c = jt * 8 + 2 * tq;
        *(float2*)&g_Wh2[g][r0][c] = make_float2(acc[jt][0], acc[jt][1]);
        *(float2*)&g_Wh2[g][r1][c] = make_float2(acc[jt][2], acc[jt][3]);
    }
    const float* ao = g ? ao2 : ao1;
    float s1r0 = 0.f, s2r0 = 0.f, s1r1 = 0.f, s2r1 = 0.f;
    #pragma unroll
    for (int jt = 0; jt < 8; jt++) {
        int c = jt * 8 + 2 * tq;
        float av0 = __ldg(ao + c),      av1 = __ldg(ao + c + 1);
        float ad0 = __ldg(ao + 64 + c), ad1 = __ldg(ao + 64 + c + 1);
        s1r0 += acc[jt][0] * av0 + acc[jt][1] * av1;
        s2r0 += acc[jt][0] * ad0 + acc[jt][1] * ad1;
        s1r1 += acc[jt][2] * av0 + acc[jt][3] * av1;
        s2r1 += acc[jt][2] * ad0 + acc[jt][3] * ad1;
    }
    #pragma unroll
    for (int off = 1; off < 4; off <<= 1) {
        s1r0 += __shfl_xor_sync(0xffffffffu, s1r0, off);
        s2r0 += __shfl_xor_sync(0xffffffffu, s2r0, off);
        s1r1 += __shfl_xor_sync(0xffffffffu, s1r1, off);
        s2r1 += __shfl_xor_sync(0xffffffffu, s2r1, off);
    }
    if (tq == 0) {
        g_s1o[g][r0] = s1r0;
        g_s2o[g][r0] = s2r0;
        g_s1o[g][r1] = s1r1;
        g_s2o[g][r1] = s2r1;
    }
}

// ---- scalar gather chunk (attn2) ----
__device__ __forceinline__ void gat_chunk2(const float* __restrict__ tab, int lim,
                                           int cj, float ej, float& ax, float& ay) {
    int kk = 0;
    for (; kk + 4 <= lim; kk += 4) {
        int   c0 = __shfl_sync(0xffffffffu, cj, kk);
        int   c1 = __shfl_sync(0xffffffffu, cj, kk + 1);
        int   c2 = __shfl_sync(0xffffffffu, cj, kk + 2);
        int   c3 = __shfl_sync(0xffffffffu, cj, kk + 3);
        float e0 = __shfl_sync(0xffffffffu, ej, kk);
        float e1 = __shfl_sync(0xffffffffu, ej, kk + 1);
        float e2 = __shfl_sync(0xffffffffu, ej, kk + 2);
        float e3 = __shfl_sync(0xffffffffu, ej, kk + 3);
        float2 v0 = *(const float2*)(tab + (size_t)c0 * 64);
        float2 v1 = *(const float2*)(tab + (size_t)c1 * 64);
        float2 v2 = *(const float2*)(tab + (size_t)c2 * 64);
        float2 v3 = *(const float2*)(tab + (size_t)c3 * 64);
        ax += e0 * v0.x + e1 * v1.x + e2 * v2.x + e3 * v3.x;
        ay += e0 * v0.y + e1 * v1.y + e2 * v2.y + e3 * v3.y;
    }
    for (; kk < lim; kk++) {
        int   c = __shfl_sync(0xffffffffu, cj, kk);
        float e = __shfl_sync(0xffffffffu, ej, kk);
        float2 v = *(const float2*)(tab + (size_t)c * 64);
        ax += e * v.x;
        ay += e * v.y;
    }
}

// =====================================================================
// Layer-2 attention + ELU + semantic fusion (round-11 proven)
// =====================================================================
__global__ void attn2_final(const float* __restrict__ Wp1, const float* __restrict__ bp1,
                            const float* __restrict__ Wp2, float* __restrict__ out) {
    int tid  = threadIdx.x;
    int lane = tid & 31;
    int w    = tid >> 5;
    int n    = w >> 1;
    int g    = w & 1;
    int i    = blockIdx.x * 4 + n;

    __shared__ float se[4][2][64];
    __shared__ float sw[4][2];

    int d = g_deg[g][i];
    float s1v = g_s1o[g][i];
    int c0 = 0, c1 = 0;
    float e0 = 0.f, e1 = 0.f;
    if (lane < d) {
        c0 = g_cols[g][i][lane];
        e0 = lkexp(s1v + g_s2o[g][c0]);
    }
    if (lane + 32 < d) {
        c1 = g_cols[g][i][lane + 32];
        e1 = lkexp(s1v + g_s2o[g][c1]);
    }
    float sum = e0 + e1;
    #pragma unroll
    for (int off = 16; off; off >>= 1) sum += __shfl_xor_sync(0xffffffffu, sum, off);
    float inv = 1.f / sum;

    const float* tab = &g_Wh2[g][0][2 * lane];
    float ax = 0.f, ay = 0.f;
    int lim0 = d < 32 ? d : 32;
    int lim1 = d - 32; lim1 = lim1 < 0 ? 0 : lim1;
    gat_chunk2(tab, lim0, c0, e0, ax, ay);
    gat_chunk2(tab, lim1, c1, e1, ax, ay);

    ax *= inv; ay *= inv;
    se[n][g][2 * lane]     = elu1(ax);
    se[n][g][2 * lane + 1] = elu1(ay);
    __syncthreads();

    if (tid < 128) {
        int pn = tid >> 5, pg = (tid >> 4) & 1, p = tid & 15;
        float s = __ldg(bp1 + p);
        #pragma unroll
        for (int f = 0; f < 64; f++) s += se[pn][pg][f] * __ldg(Wp1 + f * NPROJ + p);
        float e2x = __expf(2.f * s);
        float t = __fdividef(e2x - 1.f, e2x + 1.f);
        float wv = t * __ldg(Wp2 + p);
        wv += __shfl_xor_sync(0xffffffffu, wv, 1);
        wv += __shfl_xor_sync(0xffffffffu, wv, 2);
        wv += __shfl_xor_sync(0xffffffffu, wv, 4);
        wv += __shfl_xor_sync(0xffffffffu, wv, 8);
        if (p == 0) sw[pn][pg] = wv;
    }
    __syncthreads();

    int on = tid >> 6, f = tid & 63;
    float w0 = sw[on][0], w1 = sw[on][1];
    float mm = fmaxf(w0, w1);
    float b0 = __expf(w0 - mm), b1 = __expf(w1 - mm);
    float ib = 1.f / (b0 + b1);
    int oi = blockIdx.x * 4 + on;
    out[(size_t)oi * 64 + f] = (b0 * se[on][0][f] + b1 * se[on][1][f]) * ib;
}

// ---------------- launch ----------------
extern "C" void kernel_launch(void* const* d_in, const int* in_sizes, int n_in,
                              void* d_out, int out_size) {
    const float* x    = (const float*)d_in[0];
    const float* sadj = (const float*)d_in[1];
    const float* sadj2= (const float*)d_in[2];
    const float* W1   = (const float*)d_in[3];
    const float* a1   = (const float*)d_in[4];
    const float* Wo1  = (const float*)d_in[5];
    const float* ao1  = (const float*)d_in[6];
    const float* W2   = (const float*)d_in[7];
    const float* a2   = (const float*)d_in[8];
    const float* Wo2  = (const float*)d_in[9];
    const float* ao2  = (const float*)d_in[10];
    const float* Wp1  = (const float*)d_in[11];
    const float* bp1  = (const float*)d_in[12];
    const float* Wp2  = (const float*)d_in[13];
    float* out = (float*)d_out;

    static cudaStream_t s_side = nullptr;
    static cudaEvent_t  ev_fork = nullptr, ev_join = nullptr;
    if (!s_side) {
        cudaStreamCreateWithFlags(&s_side, cudaStreamNonBlocking);
        cudaEventCreateWithFlags(&ev_fork, cudaEventDisableTiming);
        cudaEventCreateWithFlags(&ev_join, cudaEventDisableTiming);
    }

    cudaEventRecord(ev_fork, 0);
    cudaStreamWaitEvent(s_side, ev_fork, 0);
    csr_build<<<1024, 256, 0, s_side>>>(sadj, sadj2);
    cudaEventRecord(ev_join, s_side);

    prep_all<<<1776, 256>>>(x, W1, W2, Wo1, Wo2);
    gemm1_mma<<<dim3(64, 8), 256>>>(a1, a2);

    cudaStreamWaitEvent(0, ev_join, 0);

    attn_layer1<<<2048, 256>>>();
    gemm2_mma<<<dim3(128, 2), 256>>>(ao1, ao2);
    attn2_final<<<1024, 256>>>(Wp1, bp1, Wp2, out);
}